// round 12
// baseline (speedup 1.0000x reference)
#include <cuda_runtime.h>
#include <cuda_bf16.h>
#include <cstdint>

// ---------------------------------------------------------------------------
// VQ-VAE VectorQuantizer on GB300 (sm_103, no 'a' features available in PTX).
// bf16 mma.sync approx distances -> rigorous window candidate filter ->
// exact sequential fp32-FMA refine (bit-identical to XLA, rel_err=0.0).
// R12: k_mma rebuilt at 512 threads / 16 consumer warps (4 per SMSP); each
// warp does 16 tokens x 64 codes per n-tile; A-frags per-k double-buffered
// (reg cap 128); cooperative staging; candidate lists split 8-ways.
// ---------------------------------------------------------------------------

#define N_TOK   16384
#define N_CODE  8192
#define C_DIM   256
#define Q_ELEMS 4194304      // 16*256*32*32
#define ENC_OFF 4194306LL    // 1 + Q_ELEMS + 1
#define SLOT    16           // candidate slots per (token, ch, lane-quad)
#define QPARTS  512

__device__ float          g_S[N_TOK];
__device__ float          g_L1[N_TOK];
__device__ float          g_E2[N_CODE];
__device__ int            g_idx[N_TOK];
__device__ int            g_counts[N_CODE];
__device__ double         g_loss_part[QPARTS];
__device__ int            g_cand[N_TOK][8 * SLOT];
__device__ int            g_cnt8[N_TOK][8];
__device__ unsigned       g_maxe_bits;
__device__ __nv_bfloat16  g_embh[N_CODE * C_DIM];   // bf16 codebook (4MB)

__device__ __forceinline__ float f_inf() { return __int_as_float(0x7f800000); }

__device__ __forceinline__ uint32_t smem_u32(const void* p) {
    uint32_t a;
    asm("{ .reg .u64 t; cvta.to.shared.u64 t, %1; cvt.u32.u64 %0, t; }"
        : "=r"(a) : "l"(p));
    return a;
}
#define LDSM_X4(r0, r1, r2, r3, addr)                                          \
    asm volatile("ldmatrix.sync.aligned.m8n8.x4.shared.b16 {%0,%1,%2,%3}, [%4];" \
        : "=r"(r0), "=r"(r1), "=r"(r2), "=r"(r3) : "r"(addr))
#define MMA_BF16(c0, c1, c2, c3, a0, a1, a2, a3, b0, b1)                       \
    asm volatile("mma.sync.aligned.m16n8k16.row.col.f32.bf16.bf16.f32 "       \
        "{%0,%1,%2,%3},{%4,%5,%6,%7},{%8,%9},{%0,%1,%2,%3};"                  \
        : "+f"(c0), "+f"(c1), "+f"(c2), "+f"(c3)                               \
        : "r"(a0), "r"(a1), "r"(a2), "r"(a3), "r"(b0), "r"(b1))

// ---------------------------------------------------------------- reset ----
__global__ void k_reset() {
    int t = blockIdx.x * blockDim.x + threadIdx.x;
    if (t < N_CODE) g_counts[t] = 0;
    if (t == 0)     g_maxe_bits = 0;
}

// --------------------------------------- one-time emb -> bf16 conversion ----
__global__ void k_cvt(const float* __restrict__ emb) {
    int i = blockIdx.x * blockDim.x + threadIdx.x;   // 262144 threads, 8 vals ea
    const float4 v0 = *(const float4*)&emb[(size_t)i * 8];
    const float4 v1 = *(const float4*)&emb[(size_t)i * 8 + 4];
    __nv_bfloat162 h0 = __floats2bfloat162_rn(v0.x, v0.y);
    __nv_bfloat162 h1 = __floats2bfloat162_rn(v0.z, v0.w);
    __nv_bfloat162 h2 = __floats2bfloat162_rn(v1.x, v1.y);
    __nv_bfloat162 h3 = __floats2bfloat162_rn(v1.z, v1.w);
    uint4 pk;
    pk.x = *(uint32_t*)&h0; pk.y = *(uint32_t*)&h1;
    pk.z = *(uint32_t*)&h2; pk.w = *(uint32_t*)&h3;
    *(uint4*)&g_embh[(size_t)i * 8] = pk;
}

// ----------------------------------------------- S = sum(x*x), L1 = sum|x| --
__global__ void k_S(const float* __restrict__ x) {
    int n = blockIdx.x * blockDim.x + threadIdx.x;
    if (n >= N_TOK) return;
    int b = n >> 10, hw = n & 1023;
    const float* p = x + (size_t)b * 262144 + hw;
    float acc = 0.0f, l1 = 0.0f;
    for (int c = 0; c < C_DIM; c++) {
        float v = p[(size_t)c * 1024];
        acc = __fadd_rn(acc, __fmul_rn(v, v));
        l1 += fabsf(v);
    }
    g_S[n] = acc;
    g_L1[n] = l1;
}

// ----------------------------------------- E2 = sum(e*e), track max |e| ----
__global__ void k_E2(const float* __restrict__ emb) {
    int k = blockIdx.x * blockDim.x + threadIdx.x;
    if (k >= N_CODE) return;
    const float4* p = (const float4*)(emb + (size_t)k * C_DIM);
    float acc = 0.0f, mx = 0.0f;
#pragma unroll 8
    for (int c4 = 0; c4 < C_DIM / 4; c4++) {
        float4 v = __ldg(&p[c4]);
        acc = __fadd_rn(acc, __fmul_rn(v.x, v.x));
        acc = __fadd_rn(acc, __fmul_rn(v.y, v.y));
        acc = __fadd_rn(acc, __fmul_rn(v.z, v.z));
        acc = __fadd_rn(acc, __fmul_rn(v.w, v.w));
        mx = fmaxf(mx, fmaxf(fmaxf(fabsf(v.x), fabsf(v.y)),
                             fmaxf(fabsf(v.z), fabsf(v.w))));
    }
    g_E2[k] = acc;
    atomicMax(&g_maxe_bits, __float_as_uint(mx));   // positive: uint order == float order
}

// ----------------------- bf16 mma.sync approx distances + candidate filter --
// 512 threads = 16 consumer warps (4/SMSP). Warp w: token block tb = w>>1
// (16 tokens), code half ch = w&1 (64 of the 128 codes per n-tile).
// A per-k LDSM double-buffered; all warps cooperatively stage the next E.
#define RS      528              // padded row stride bytes (264 halves)
#define SM_E2S  0                // 2 x 128 f32
#define SM_A    1024             // 128 rows * 528B = 67584
#define SM_EB0  68608
#define SM_EB1  136192
#define SMEM_DYN 203776

__global__ void __launch_bounds__(512, 1)
k_mma(const float* __restrict__ x) {
    extern __shared__ char sm[];
    float* e2s = (float*)(sm + SM_E2S);
    const uint32_t sb = smem_u32(sm);
    const uint32_t sA = sb + SM_A;

    const int tid = threadIdx.x, w = tid >> 5, lane = tid & 31;
    const int mbase = blockIdx.x * 128;
    const int b     = mbase >> 10;
    const int hw0   = mbase & 1023;
    const float* xb = x + (size_t)b * 262144 + hw0;

    // ---- stage A: 128 tokens x 256 c, bf16, padded rows (all 512 threads) --
    for (int i = tid; i < 128 * 32; i += 512) {
        int m = i & 127, c0 = (i >> 7) * 8;
        float v0 = xb[(size_t)(c0 + 0) * 1024 + m];
        float v1 = xb[(size_t)(c0 + 1) * 1024 + m];
        float v2 = xb[(size_t)(c0 + 2) * 1024 + m];
        float v3 = xb[(size_t)(c0 + 3) * 1024 + m];
        float v4 = xb[(size_t)(c0 + 4) * 1024 + m];
        float v5 = xb[(size_t)(c0 + 5) * 1024 + m];
        float v6 = xb[(size_t)(c0 + 6) * 1024 + m];
        float v7 = xb[(size_t)(c0 + 7) * 1024 + m];
        __nv_bfloat162 h0 = __floats2bfloat162_rn(v0, v1);
        __nv_bfloat162 h1 = __floats2bfloat162_rn(v2, v3);
        __nv_bfloat162 h2 = __floats2bfloat162_rn(v4, v5);
        __nv_bfloat162 h3 = __floats2bfloat162_rn(v6, v7);
        uint4 pk;
        pk.x = *(uint32_t*)&h0; pk.y = *(uint32_t*)&h1;
        pk.z = *(uint32_t*)&h2; pk.w = *(uint32_t*)&h3;
        *(uint4*)(sm + SM_A + m * RS + c0 * 2) = pk;
    }

    // ---- E tile copy from bf16 codebook (pure 16B moves) ----
    auto stage_E = [&](int nt, int buf) {
        const int kb = nt * 128;
        char* eb = sm + (buf ? SM_EB1 : SM_EB0);
        for (int i = tid; i < 4096; i += 512) {          // 128 rows x 32 chunks
            int row = i >> 5, c16 = (i & 31);
            uint4 v = *(const uint4*)&g_embh[(size_t)(kb + row) * 256 + c16 * 8];
            *(uint4*)(eb + row * RS + c16 * 16) = v;
        }
        if (tid < 128) e2s[buf * 128 + tid] = g_E2[kb + tid];
    };

    stage_E(0, 0);
    __syncthreads();

    const int tb = w >> 1;          // token block 0..7
    const int ch = w & 1;           // code half 0..1
    const uint32_t abase = sA + (uint32_t)(tb * 16 + (lane & 15)) * RS
                              + ((lane >> 4) & 1) * 16;

    const int   tok0 = mbase + tb * 16 + (lane >> 2);
    const int   tok1 = tok0 + 8;
    const int   sub  = (ch * 4 + (lane & 3)) * SLOT;
    const float S0 = g_S[tok0], S1 = g_S[tok1];
    const float maxe = __uint_as_float(g_maxe_bits);
    const float W0 = __fmaf_rn(0.0313f * maxe, g_L1[tok0], 1.3e-4f);
    const float W1 = __fmaf_rn(0.0313f * maxe, g_L1[tok1], 1.3e-4f);
    float rm0 = f_inf(), rm1 = f_inf(), thr0 = f_inf(), thr1 = f_inf();
    int   c0n = 0, c1n = 0;

    for (int nt = 0; nt < 64; nt++) {
        // cooperative prefetch of the next E tile (overlaps with compute)
        if (nt + 1 < 64) stage_E(nt + 1, (nt + 1) & 1);

        const uint32_t eB = sb + ((nt & 1) ? SM_EB1 : SM_EB0);
        const float*   e2 = e2s + (nt & 1) * 128;
        const int      kb = nt * 128;
        const uint32_t bbase = eB + (uint32_t)(ch * 64 + (lane & 15)) * RS
                                  + ((lane >> 4) & 1) * 16;

        float acc[4][8];
#pragma unroll
        for (int q = 0; q < 4; q++)
#pragma unroll
            for (int r = 0; r < 8; r++) acc[q][r] = 0.f;

        // A-fragment double buffer over k
        uint32_t a[2][4];
        LDSM_X4(a[0][0], a[0][1], a[0][2], a[0][3], abase);
#pragma unroll
        for (int k = 0; k < 16; k++) {
            const int p = k & 1;
            if (k < 15)
                LDSM_X4(a[p ^ 1][0], a[p ^ 1][1], a[p ^ 1][2], a[p ^ 1][3],
                        abase + (k + 1) * 32);
#pragma unroll
            for (int q = 0; q < 4; q++) {
                uint32_t b0, b1, b2, b3;
                LDSM_X4(b0, b1, b2, b3, bbase + (uint32_t)q * (16 * RS) + k * 32);
                MMA_BF16(acc[q][0], acc[q][1], acc[q][2], acc[q][3],
                         a[p][0], a[p][1], a[p][2], a[p][3], b0, b2);
                MMA_BF16(acc[q][4], acc[q][5], acc[q][6], acc[q][7],
                         a[p][0], a[p][1], a[p][2], a[p][3], b1, b3);
            }
        }

        // epilogue: d = (S + E2) - 2*dot ; atomic-free candidate capture
#pragma unroll
        for (int q = 0; q < 4; q++) {
#pragma unroll
            for (int h = 0; h < 2; h++) {
                const int   cA  = ch * 64 + (q * 2 + h) * 8 + (lane & 3) * 2;
                const float e2a = e2[cA], e2b = e2[cA + 1];
                const int   colA = kb + cA, colB = colA + 1;
                const float dotA0 = h ? acc[q][4] : acc[q][0];
                const float dotB0 = h ? acc[q][5] : acc[q][1];
                const float dotA1 = h ? acc[q][6] : acc[q][2];
                const float dotB1 = h ? acc[q][7] : acc[q][3];
                float dA0 = __fsub_rn(__fadd_rn(S0, e2a), __fmul_rn(2.0f, dotA0));
                float dB0 = __fsub_rn(__fadd_rn(S0, e2b), __fmul_rn(2.0f, dotB0));
                float dA1 = __fsub_rn(__fadd_rn(S1, e2a), __fmul_rn(2.0f, dotA1));
                float dB1 = __fsub_rn(__fadd_rn(S1, e2b), __fmul_rn(2.0f, dotB1));
                if (dA0 < thr0) {
                    if (c0n < SLOT) g_cand[tok0][sub + c0n] = colA;
                    c0n++;
                    if (dA0 < rm0) { rm0 = dA0; thr0 = __fadd_rn(dA0, W0); }
                }
                if (dB0 < thr0) {
                    if (c0n < SLOT) g_cand[tok0][sub + c0n] = colB;
                    c0n++;
                    if (dB0 < rm0) { rm0 = dB0; thr0 = __fadd_rn(dB0, W0); }
                }
                if (dA1 < thr1) {
                    if (c1n < SLOT) g_cand[tok1][sub + c1n] = colA;
                    c1n++;
                    if (dA1 < rm1) { rm1 = dA1; thr1 = __fadd_rn(dA1, W1); }
                }
                if (dB1 < thr1) {
                    if (c1n < SLOT) g_cand[tok1][sub + c1n] = colB;
                    c1n++;
                    if (dB1 < rm1) { rm1 = dB1; thr1 = __fadd_rn(dB1, W1); }
                }
            }
        }
        // tighten thresholds across the 4 lanes sharing the same token rows
#pragma unroll
        for (int off = 1; off < 4; off <<= 1) {
            rm0 = fminf(rm0, __shfl_xor_sync(0xffffffff, rm0, off));
            rm1 = fminf(rm1, __shfl_xor_sync(0xffffffff, rm1, off));
        }
        thr0 = __fadd_rn(rm0, W0);
        thr1 = __fadd_rn(rm1, W1);
        __syncthreads();
    }

    g_cnt8[tok0][ch * 4 + (lane & 3)] = c0n;
    g_cnt8[tok1][ch * 4 + (lane & 3)] = c1n;
}

// ------------------------------------- exact refinement (bit-exact argmin) --
__global__ void k_refine(const float* __restrict__ x, const float* __restrict__ emb) {
    __shared__ float xs[8][256];
    const int w = threadIdx.x >> 5, lane = threadIdx.x & 31;
    const int n = blockIdx.x * 8 + w;
    const int b = n >> 10, hw = n & 1023;
    const float* xb = x + (size_t)b * 262144 + hw;
    for (int c = lane; c < 256; c += 32) xs[w][c] = xb[(size_t)c * 1024];
    __syncwarp();

    const float S = g_S[n];
    int c8[8];
    bool ovf = false;
    int total = 0;
#pragma unroll
    for (int i = 0; i < 8; i++) {
        c8[i] = g_cnt8[n][i];
        ovf |= (c8[i] > SLOT);
        total += c8[i];
    }
    float bd = f_inf(); int bi = 0x7fffffff;

    auto exact_d = [&](int k) -> float {
        const float4* e = (const float4*)(emb + (size_t)k * 256);
        const float4* xv4 = (const float4*)xs[w];
        float acc = 0.0f;
#pragma unroll 8
        for (int c4i = 0; c4i < 64; c4i++) {
            float4 ev = __ldg(&e[c4i]);
            float4 xv = xv4[c4i];
            acc = __fmaf_rn(xv.x, ev.x, acc);
            acc = __fmaf_rn(xv.y, ev.y, acc);
            acc = __fmaf_rn(xv.z, ev.z, acc);
            acc = __fmaf_rn(xv.w, ev.w, acc);
        }
        float t = __fadd_rn(S, g_E2[k]);
        return __fsub_rn(t, __fmul_rn(2.0f, acc));
    };

    if (ovf) {                                          // overflow: full scan
        for (int k = lane; k < N_CODE; k += 32) {
            float d = exact_d(k);
            if (d < bd || (d == bd && k < bi)) { bd = d; bi = k; }
        }
    } else {
        for (int ci = lane; ci < total; ci += 32) {
            int r = ci, p = 0;
            while (r >= c8[p]) { r -= c8[p]; p++; }
            int k = g_cand[n][p * SLOT + r];
            float d = exact_d(k);
            if (d < bd || (d == bd && k < bi)) { bd = d; bi = k; }
        }
    }
#pragma unroll
    for (int off = 16; off > 0; off >>= 1) {
        float od = __shfl_down_sync(0xffffffff, bd, off);
        int   oi = __shfl_down_sync(0xffffffff, bi, off);
        if (od < bd || (od == bd && oi < bi)) { bd = od; bi = oi; }
    }
    if (lane == 0) g_idx[n] = bi;
}

// ---------------- quantized output + loss partial (smem row-gather) ---------
__global__ void __launch_bounds__(256)
k_quant(const float* __restrict__ x, const float* __restrict__ emb,
        float* __restrict__ outq) {
    __shared__ float  er[32][257];
    __shared__ int    sidx[32];
    __shared__ double sred[256];
    const int tid = threadIdx.x;
    const int n0  = blockIdx.x * 32;
    const int b   = n0 >> 10;
    const int hw0 = n0 & 1023;

    if (tid < 32) sidx[tid] = g_idx[n0 + tid];
    __syncthreads();
    for (int i = tid; i < 32 * 64; i += 256) {          // float4 gather
        int row = i >> 6, c4i = i & 63;
        float4 v = __ldg((const float4*)&emb[(size_t)sidx[row] * 256 + c4i * 4]);
        er[row][c4i * 4 + 0] = v.x;
        er[row][c4i * 4 + 1] = v.y;
        er[row][c4i * 4 + 2] = v.z;
        er[row][c4i * 4 + 3] = v.w;
    }
    __syncthreads();

    const int hwl = tid & 31;
    double part = 0.0;
    for (int c = tid >> 5; c < 256; c += 8) {
        size_t l = (size_t)b * 262144 + (size_t)c * 1024 + hw0 + hwl;
        float xv   = x[l];
        float q    = er[hwl][c];
        float diff = __fsub_rn(q, xv);
        outq[l]    = __fadd_rn(xv, diff);               // straight-through
        part += (double)__fmul_rn(diff, diff);
    }

    sred[tid] = part;
    __syncthreads();
    for (int s = 128; s > 0; s >>= 1) {
        if (tid < s) sred[tid] += sred[tid + s];
        __syncthreads();
    }
    if (tid == 0) g_loss_part[blockIdx.x] = sred[0];
}

// --------------- fused encodings zero + one-hot scatter + histogram ---------
__global__ void __launch_bounds__(256)
k_enc(float* __restrict__ out) {
    const int w    = threadIdx.x >> 5, lane = threadIdx.x & 31;
    const int row  = blockIdx.x * 8 + w;
    const int idx  = g_idx[row];
    float2* dst = (float2*)(out + ENC_OFF) + (size_t)row * 4096;
    const int hot = idx >> 1;
    const float2 z = make_float2(0.0f, 0.0f);
#pragma unroll 8
    for (int j = 0; j < 128; j++) {
        int pos = j * 32 + lane;
        float2 v = z;
        if (pos == hot) {                                // rare: once per warp
            if (idx & 1) v.y = 1.0f; else v.x = 1.0f;
        }
        dst[pos] = v;
    }
    if (lane == 0) atomicAdd(&g_counts[idx], 1);
}

// -------------------------------------------------- loss + perplexity -------
__global__ void k_final(float* __restrict__ out, int has_full) {
    __shared__ double sred[256];
    int t = threadIdx.x;
    double acc = 0.0;
    for (int k = t; k < N_CODE; k += 256) {
        float p  = (float)g_counts[k] * (1.0f / 16384.0f);
        float lg = logf(__fadd_rn(p, 1e-10f));
        acc += (double)__fmul_rn(p, lg);
    }
    sred[t] = acc; __syncthreads();
    for (int s = 128; s > 0; s >>= 1) {
        if (t < s) sred[t] += sred[t + s];
        __syncthreads();
    }
    double H = sred[0];

    double lacc = 0.0;
    for (int k = t; k < QPARTS; k += 256) lacc += g_loss_part[k];
    __syncthreads();
    sred[t] = lacc; __syncthreads();
    for (int s = 128; s > 0; s >>= 1) {
        if (t < s) sred[t] += sred[t + s];
        __syncthreads();
    }
    if (t == 0) {
        float m    = (float)(sred[0] / (double)Q_ELEMS);
        float loss = __fadd_rn(m, __fmul_rn(0.25f, m));
        out[0] = loss;
        if (has_full) out[1 + Q_ELEMS] = expf(-(float)H);
    }
}

// ---------------------------------------------------------------------------
extern "C" void kernel_launch(void* const* d_in, const int* in_sizes, int n_in,
                              void* d_out, int out_size) {
    const float* x   = (const float*)d_in[0];
    const float* emb = (const float*)d_in[1];
    if (n_in >= 2 && in_sizes[0] == N_CODE * C_DIM && in_sizes[1] == Q_ELEMS) {
        const float* t = x; x = emb; emb = t;
    }
    float* out = (float*)d_out;

    long long enc_elems = (long long)out_size - ENC_OFF;
    int has_full = (enc_elems >= (long long)N_TOK * N_CODE);

    cudaFuncSetAttribute(k_mma, cudaFuncAttributeMaxDynamicSharedMemorySize,
                         SMEM_DYN);

    k_reset <<<32, 256>>>();
    k_cvt   <<<1024, 256>>>(emb);
    k_S     <<<N_TOK / 256, 256>>>(x);
    k_E2    <<<64, 128>>>(emb);
    k_mma   <<<N_TOK / 128, 512, SMEM_DYN>>>(x);
    k_refine<<<N_TOK / 8, 256>>>(x, emb);
    k_quant <<<QPARTS, 256>>>(x, emb, out + 1);
    if (has_full)
        k_enc<<<N_TOK / 8, 256>>>(out);
    else if (enc_elems > 0)
        cudaMemsetAsync(out + ENC_OFF, 0, (size_t)enc_elems * sizeof(float), 0);
    k_final <<<1, 256>>>(out, has_full);
}

// round 13
// speedup vs baseline: 6.5656x; 6.5656x over previous
#include <cuda_runtime.h>
#include <cuda_bf16.h>
#include <cstdint>

// ---------------------------------------------------------------------------
// VQ-VAE VectorQuantizer on GB300 (sm_103, no 'a' features available in PTX).
// bf16 mma.sync approx distances -> rigorous window candidate filter ->
// exact sequential fp32-FMA refine (bit-identical to XLA, rel_err=0.0).
// R13: revert k_mma to R11 (384-thr warp-specialized; R12's 512-thr variant
// spilled registers at the 128-reg cap). Encodings zeroing fused into k_mma
// (DRAM idle there); k_enc now writes only the hot elements.
// ---------------------------------------------------------------------------

#define N_TOK   16384
#define N_CODE  8192
#define C_DIM   256
#define Q_ELEMS 4194304      // 16*256*32*32
#define ENC_OFF 4194306LL    // 1 + Q_ELEMS + 1
#define SLOT    32           // candidate slots per (token, lane-quad position)
#define QPARTS  512

__device__ float          g_S[N_TOK];
__device__ float          g_L1[N_TOK];
__device__ float          g_E2[N_CODE];
__device__ int            g_idx[N_TOK];
__device__ int            g_counts[N_CODE];
__device__ double         g_loss_part[QPARTS];
__device__ int            g_cand[N_TOK][4 * SLOT];
__device__ int            g_cnt4[N_TOK][4];
__device__ unsigned       g_maxe_bits;
__device__ __nv_bfloat16  g_embh[N_CODE * C_DIM];   // bf16 codebook (4MB)

__device__ __forceinline__ float f_inf() { return __int_as_float(0x7f800000); }

__device__ __forceinline__ uint32_t smem_u32(const void* p) {
    uint32_t a;
    asm("{ .reg .u64 t; cvta.to.shared.u64 t, %1; cvt.u32.u64 %0, t; }"
        : "=r"(a) : "l"(p));
    return a;
}
#define LDSM_X4(r0, r1, r2, r3, addr)                                          \
    asm volatile("ldmatrix.sync.aligned.m8n8.x4.shared.b16 {%0,%1,%2,%3}, [%4];" \
        : "=r"(r0), "=r"(r1), "=r"(r2), "=r"(r3) : "r"(addr))
#define MMA_BF16(c0, c1, c2, c3, a0, a1, a2, a3, b0, b1)                       \
    asm volatile("mma.sync.aligned.m16n8k16.row.col.f32.bf16.bf16.f32 "       \
        "{%0,%1,%2,%3},{%4,%5,%6,%7},{%8,%9},{%0,%1,%2,%3};"                  \
        : "+f"(c0), "+f"(c1), "+f"(c2), "+f"(c3)                               \
        : "r"(a0), "r"(a1), "r"(a2), "r"(a3), "r"(b0), "r"(b1))

// ---------------------------------------------------------------- reset ----
__global__ void k_reset() {
    int t = blockIdx.x * blockDim.x + threadIdx.x;
    if (t < N_CODE) g_counts[t] = 0;
    if (t == 0)     g_maxe_bits = 0;
}

// --------------------------------------- one-time emb -> bf16 conversion ----
__global__ void k_cvt(const float* __restrict__ emb) {
    int i = blockIdx.x * blockDim.x + threadIdx.x;   // 262144 threads, 8 vals ea
    const float4 v0 = *(const float4*)&emb[(size_t)i * 8];
    const float4 v1 = *(const float4*)&emb[(size_t)i * 8 + 4];
    __nv_bfloat162 h0 = __floats2bfloat162_rn(v0.x, v0.y);
    __nv_bfloat162 h1 = __floats2bfloat162_rn(v0.z, v0.w);
    __nv_bfloat162 h2 = __floats2bfloat162_rn(v1.x, v1.y);
    __nv_bfloat162 h3 = __floats2bfloat162_rn(v1.z, v1.w);
    uint4 pk;
    pk.x = *(uint32_t*)&h0; pk.y = *(uint32_t*)&h1;
    pk.z = *(uint32_t*)&h2; pk.w = *(uint32_t*)&h3;
    *(uint4*)&g_embh[(size_t)i * 8] = pk;
}

// ----------------------------------------------- S = sum(x*x), L1 = sum|x| --
__global__ void k_S(const float* __restrict__ x) {
    int n = blockIdx.x * blockDim.x + threadIdx.x;
    if (n >= N_TOK) return;
    int b = n >> 10, hw = n & 1023;
    const float* p = x + (size_t)b * 262144 + hw;
    float acc = 0.0f, l1 = 0.0f;
    for (int c = 0; c < C_DIM; c++) {
        float v = p[(size_t)c * 1024];
        acc = __fadd_rn(acc, __fmul_rn(v, v));
        l1 += fabsf(v);
    }
    g_S[n] = acc;
    g_L1[n] = l1;
}

// ----------------------------------------- E2 = sum(e*e), track max |e| ----
__global__ void k_E2(const float* __restrict__ emb) {
    int k = blockIdx.x * blockDim.x + threadIdx.x;
    if (k >= N_CODE) return;
    const float4* p = (const float4*)(emb + (size_t)k * C_DIM);
    float acc = 0.0f, mx = 0.0f;
#pragma unroll 8
    for (int c4 = 0; c4 < C_DIM / 4; c4++) {
        float4 v = __ldg(&p[c4]);
        acc = __fadd_rn(acc, __fmul_rn(v.x, v.x));
        acc = __fadd_rn(acc, __fmul_rn(v.y, v.y));
        acc = __fadd_rn(acc, __fmul_rn(v.z, v.z));
        acc = __fadd_rn(acc, __fmul_rn(v.w, v.w));
        mx = fmaxf(mx, fmaxf(fmaxf(fabsf(v.x), fabsf(v.y)),
                             fmaxf(fabsf(v.z), fabsf(v.w))));
    }
    g_E2[k] = acc;
    atomicMax(&g_maxe_bits, __float_as_uint(mx));   // positive: uint order == float order
}

// ----------------------- bf16 mma.sync approx distances + candidate filter --
// 384 threads: warps 0-7 = MMA+epilogue (consumers), warps 8-11 = E staging
// (producers; exactly 1 per SMSP). A resident in smem, E double-buffered.
// Also zeroes this CTA's 4MB slice of the encodings output (DRAM idle here).
#define RS      528              // padded row stride bytes (264 halves)
#define SM_E2S  0                // 2 x 128 f32
#define SM_A    1024             // 128 rows * 528B = 67584
#define SM_EB0  68608
#define SM_EB1  136192
#define SMEM_DYN 203776

__global__ void __launch_bounds__(384, 1)
k_mma(const float* __restrict__ x, float* __restrict__ out, int zero_enc) {
    extern __shared__ char sm[];
    float* e2s = (float*)(sm + SM_E2S);
    const uint32_t sb = smem_u32(sm);
    const uint32_t sA = sb + SM_A;

    const int tid = threadIdx.x, w = tid >> 5, lane = tid & 31;
    const int mbase = blockIdx.x * 128;
    const int b     = mbase >> 10;
    const int hw0   = mbase & 1023;
    const float* xb = x + (size_t)b * 262144 + hw0;

    // ---- zero this CTA's encodings slice (128 rows x 8192 f32 = 4MB) ------
    // Fire-and-forget stores; absorbed under compute (DRAM otherwise idle).
    if (zero_enc) {
        float2* dst = (float2*)(out + ENC_OFF) + (size_t)blockIdx.x * 524288;
        const float2 z = make_float2(0.0f, 0.0f);
        for (int i = tid; i < 524288; i += 384) dst[i] = z;
    }

    // ---- stage A: 128 tokens x 256 c, bf16, padded rows (all 384 threads) --
    for (int i = tid; i < 128 * 32; i += 384) {
        int m = i & 127, c0 = (i >> 7) * 8;
        float v0 = xb[(size_t)(c0 + 0) * 1024 + m];
        float v1 = xb[(size_t)(c0 + 1) * 1024 + m];
        float v2 = xb[(size_t)(c0 + 2) * 1024 + m];
        float v3 = xb[(size_t)(c0 + 3) * 1024 + m];
        float v4 = xb[(size_t)(c0 + 4) * 1024 + m];
        float v5 = xb[(size_t)(c0 + 5) * 1024 + m];
        float v6 = xb[(size_t)(c0 + 6) * 1024 + m];
        float v7 = xb[(size_t)(c0 + 7) * 1024 + m];
        __nv_bfloat162 h0 = __floats2bfloat162_rn(v0, v1);
        __nv_bfloat162 h1 = __floats2bfloat162_rn(v2, v3);
        __nv_bfloat162 h2 = __floats2bfloat162_rn(v4, v5);
        __nv_bfloat162 h3 = __floats2bfloat162_rn(v6, v7);
        uint4 pk;
        pk.x = *(uint32_t*)&h0; pk.y = *(uint32_t*)&h1;
        pk.z = *(uint32_t*)&h2; pk.w = *(uint32_t*)&h3;
        *(uint4*)(sm + SM_A + m * RS + c0 * 2) = pk;
    }

    // ---- E tile copy from bf16 codebook (pure 16B moves) ----
    auto stage_E = [&](int nt, int buf, int t0, int nth) {
        const int kb = nt * 128;
        char* eb = sm + (buf ? SM_EB1 : SM_EB0);
        for (int i = t0; i < 4096; i += nth) {           // 128 rows x 32 chunks
            int row = i >> 5, c16 = (i & 31);
            uint4 v = *(const uint4*)&g_embh[(size_t)(kb + row) * 256 + c16 * 8];
            *(uint4*)(eb + row * RS + c16 * 16) = v;
        }
        for (int i = t0; i < 128; i += nth) e2s[buf * 128 + i] = g_E2[kb + i];
    };

    stage_E(0, 0, tid, 384);
    __syncthreads();

    if (w >= 8) {
        // ----------------------------- producer warps: stage ahead ---------
        const int pt = tid - 256;                        // 0..127
        for (int nt = 0; nt < 64; nt++) {
            if (nt + 1 < 64) stage_E(nt + 1, (nt + 1) & 1, pt, 128);
            __syncthreads();
        }
        return;
    }

    // --------------------------------- consumer warps: MMA + filter --------
    // hoist A fragments: 16 k-steps x 4 regs
    uint32_t a[16][4];
    {
        uint32_t abase = sA + (uint32_t)(w * 16 + (lane & 15)) * RS + ((lane >> 4) & 1) * 16;
#pragma unroll
        for (int k = 0; k < 16; k++)
            LDSM_X4(a[k][0], a[k][1], a[k][2], a[k][3], abase + k * 32);
    }

    const int   tok0 = mbase + w * 16 + (lane >> 2);
    const int   tok1 = tok0 + 8;
    const int   sub  = (lane & 3) * SLOT;
    const float S0 = g_S[tok0], S1 = g_S[tok1];
    const float maxe = __uint_as_float(g_maxe_bits);
    const float W0 = __fmaf_rn(0.0313f * maxe, g_L1[tok0], 1.3e-4f);
    const float W1 = __fmaf_rn(0.0313f * maxe, g_L1[tok1], 1.3e-4f);
    float rm0 = f_inf(), rm1 = f_inf(), thr0 = f_inf(), thr1 = f_inf();
    int   c0n = 0, c1n = 0;

    for (int nt = 0; nt < 64; nt++) {
        const uint32_t eB = sb + ((nt & 1) ? SM_EB1 : SM_EB0);
        const float*   e2 = e2s + (nt & 1) * 128;
        const int      kb = nt * 128;
        const uint32_t bbase = eB + (uint32_t)(lane & 15) * RS + ((lane >> 4) & 1) * 16;

#pragma unroll 1
        for (int fq = 0; fq < 2; fq++) {
            float acc[4][8];
#pragma unroll
            for (int q = 0; q < 4; q++)
#pragma unroll
                for (int r = 0; r < 8; r++) acc[q][r] = 0.f;

            const uint32_t bq = bbase + (uint32_t)fq * (64 * RS);

            uint32_t bb[2][4][4];
#pragma unroll
            for (int q = 0; q < 4; q++)
                LDSM_X4(bb[0][q][0], bb[0][q][1], bb[0][q][2], bb[0][q][3],
                        bq + (uint32_t)q * (16 * RS));
#pragma unroll
            for (int k = 0; k < 16; k++) {
                const int p = k & 1;
                if (k < 15) {
#pragma unroll
                    for (int q = 0; q < 4; q++)
                        LDSM_X4(bb[p ^ 1][q][0], bb[p ^ 1][q][1],
                                bb[p ^ 1][q][2], bb[p ^ 1][q][3],
                                bq + (uint32_t)q * (16 * RS) + (k + 1) * 32);
                }
#pragma unroll
                for (int q = 0; q < 4; q++) {
                    MMA_BF16(acc[q][0], acc[q][1], acc[q][2], acc[q][3],
                             a[k][0], a[k][1], a[k][2], a[k][3],
                             bb[p][q][0], bb[p][q][2]);
                    MMA_BF16(acc[q][4], acc[q][5], acc[q][6], acc[q][7],
                             a[k][0], a[k][1], a[k][2], a[k][3],
                             bb[p][q][1], bb[p][q][3]);
                }
            }

            // epilogue: d = (S + E2) - 2*dot ; atomic-free candidate capture
#pragma unroll
            for (int q = 0; q < 4; q++) {
                const int fp = fq * 4 + q;
#pragma unroll
                for (int h = 0; h < 2; h++) {
                    const int   f   = fp * 2 + h;
                    const int   cA  = f * 8 + (lane & 3) * 2;
                    const float e2a = e2[cA], e2b = e2[cA + 1];
                    const int   colA = kb + cA, colB = colA + 1;
                    const float dotA0 = h ? acc[q][4] : acc[q][0];
                    const float dotB0 = h ? acc[q][5] : acc[q][1];
                    const float dotA1 = h ? acc[q][6] : acc[q][2];
                    const float dotB1 = h ? acc[q][7] : acc[q][3];
                    float dA0 = __fsub_rn(__fadd_rn(S0, e2a), __fmul_rn(2.0f, dotA0));
                    float dB0 = __fsub_rn(__fadd_rn(S0, e2b), __fmul_rn(2.0f, dotB0));
                    float dA1 = __fsub_rn(__fadd_rn(S1, e2a), __fmul_rn(2.0f, dotA1));
                    float dB1 = __fsub_rn(__fadd_rn(S1, e2b), __fmul_rn(2.0f, dotB1));
                    if (dA0 < thr0) {
                        if (c0n < SLOT) g_cand[tok0][sub + c0n] = colA;
                        c0n++;
                        if (dA0 < rm0) { rm0 = dA0; thr0 = __fadd_rn(dA0, W0); }
                    }
                    if (dB0 < thr0) {
                        if (c0n < SLOT) g_cand[tok0][sub + c0n] = colB;
                        c0n++;
                        if (dB0 < rm0) { rm0 = dB0; thr0 = __fadd_rn(dB0, W0); }
                    }
                    if (dA1 < thr1) {
                        if (c1n < SLOT) g_cand[tok1][sub + c1n] = colA;
                        c1n++;
                        if (dA1 < rm1) { rm1 = dA1; thr1 = __fadd_rn(dA1, W1); }
                    }
                    if (dB1 < thr1) {
                        if (c1n < SLOT) g_cand[tok1][sub + c1n] = colB;
                        c1n++;
                        if (dB1 < rm1) { rm1 = dB1; thr1 = __fadd_rn(dB1, W1); }
                    }
                }
            }
            // tighten thresholds across the 4 lanes sharing the token rows
#pragma unroll
            for (int off = 1; off < 4; off <<= 1) {
                rm0 = fminf(rm0, __shfl_xor_sync(0xffffffff, rm0, off));
                rm1 = fminf(rm1, __shfl_xor_sync(0xffffffff, rm1, off));
            }
            thr0 = __fadd_rn(rm0, W0);
            thr1 = __fadd_rn(rm1, W1);
        }
        __syncthreads();
    }

    g_cnt4[tok0][lane & 3] = c0n;
    g_cnt4[tok1][lane & 3] = c1n;
}

// ------------------------------------- exact refinement (bit-exact argmin) --
__global__ void k_refine(const float* __restrict__ x, const float* __restrict__ emb) {
    __shared__ float xs[8][256];
    const int w = threadIdx.x >> 5, lane = threadIdx.x & 31;
    const int n = blockIdx.x * 8 + w;
    const int b = n >> 10, hw = n & 1023;
    const float* xb = x + (size_t)b * 262144 + hw;
    for (int c = lane; c < 256; c += 32) xs[w][c] = xb[(size_t)c * 1024];
    __syncwarp();

    const float S = g_S[n];
    int c4[4];
    c4[0] = g_cnt4[n][0]; c4[1] = g_cnt4[n][1];
    c4[2] = g_cnt4[n][2]; c4[3] = g_cnt4[n][3];
    const bool ovf = (c4[0] > SLOT) | (c4[1] > SLOT) | (c4[2] > SLOT) | (c4[3] > SLOT);
    const int total = c4[0] + c4[1] + c4[2] + c4[3];
    float bd = f_inf(); int bi = 0x7fffffff;

    auto exact_d = [&](int k) -> float {
        const float4* e = (const float4*)(emb + (size_t)k * 256);
        const float4* xv4 = (const float4*)xs[w];
        float acc = 0.0f;
#pragma unroll 8
        for (int c4i = 0; c4i < 64; c4i++) {
            float4 ev = __ldg(&e[c4i]);
            float4 xv = xv4[c4i];
            acc = __fmaf_rn(xv.x, ev.x, acc);
            acc = __fmaf_rn(xv.y, ev.y, acc);
            acc = __fmaf_rn(xv.z, ev.z, acc);
            acc = __fmaf_rn(xv.w, ev.w, acc);
        }
        float t = __fadd_rn(S, g_E2[k]);
        return __fsub_rn(t, __fmul_rn(2.0f, acc));
    };

    if (ovf) {                                          // overflow: full scan
        for (int k = lane; k < N_CODE; k += 32) {
            float d = exact_d(k);
            if (d < bd || (d == bd && k < bi)) { bd = d; bi = k; }
        }
    } else {
        for (int ci = lane; ci < total; ci += 32) {
            int r = ci, p = 0;
            while (r >= c4[p]) { r -= c4[p]; p++; }
            int k = g_cand[n][p * SLOT + r];
            float d = exact_d(k);
            if (d < bd || (d == bd && k < bi)) { bd = d; bi = k; }
        }
    }
#pragma unroll
    for (int off = 16; off > 0; off >>= 1) {
        float od = __shfl_down_sync(0xffffffff, bd, off);
        int   oi = __shfl_down_sync(0xffffffff, bi, off);
        if (od < bd || (od == bd && oi < bi)) { bd = od; bi = oi; }
    }
    if (lane == 0) g_idx[n] = bi;
}

// ---------------- quantized output + loss partial (smem row-gather) ---------
__global__ void __launch_bounds__(256)
k_quant(const float* __restrict__ x, const float* __restrict__ emb,
        float* __restrict__ outq) {
    __shared__ float  er[32][257];
    __shared__ int    sidx[32];
    __shared__ double sred[256];
    const int tid = threadIdx.x;
    const int n0  = blockIdx.x * 32;
    const int b   = n0 >> 10;
    const int hw0 = n0 & 1023;

    if (tid < 32) sidx[tid] = g_idx[n0 + tid];
    __syncthreads();
    for (int i = tid; i < 32 * 64; i += 256) {          // float4 gather
        int row = i >> 6, c4i = i & 63;
        float4 v = __ldg((const float4*)&emb[(size_t)sidx[row] * 256 + c4i * 4]);
        er[row][c4i * 4 + 0] = v.x;
        er[row][c4i * 4 + 1] = v.y;
        er[row][c4i * 4 + 2] = v.z;
        er[row][c4i * 4 + 3] = v.w;
    }
    __syncthreads();

    const int hwl = tid & 31;
    double part = 0.0;
    for (int c = tid >> 5; c < 256; c += 8) {
        size_t l = (size_t)b * 262144 + (size_t)c * 1024 + hw0 + hwl;
        float xv   = x[l];
        float q    = er[hwl][c];
        float diff = __fsub_rn(q, xv);
        outq[l]    = __fadd_rn(xv, diff);               // straight-through
        part += (double)__fmul_rn(diff, diff);
    }

    sred[tid] = part;
    __syncthreads();
    for (int s = 128; s > 0; s >>= 1) {
        if (tid < s) sred[tid] += sred[tid + s];
        __syncthreads();
    }
    if (tid == 0) g_loss_part[blockIdx.x] = sred[0];
}

// ------------- hot-element one-hot scatter + histogram (zeroing in k_mma) ---
__global__ void k_enc(float* __restrict__ out, long long enc_elems) {
    int n = blockIdx.x * blockDim.x + threadIdx.x;
    if (n >= N_TOK) return;
    int idx = g_idx[n];
    long long off = (long long)n * N_CODE + idx;
    if (off < enc_elems) out[ENC_OFF + off] = 1.0f;
    atomicAdd(&g_counts[idx], 1);
}

// -------------------------------------------------- loss + perplexity -------
__global__ void k_final(float* __restrict__ out, int has_full) {
    __shared__ double sred[256];
    int t = threadIdx.x;
    double acc = 0.0;
    for (int k = t; k < N_CODE; k += 256) {
        float p  = (float)g_counts[k] * (1.0f / 16384.0f);
        float lg = logf(__fadd_rn(p, 1e-10f));
        acc += (double)__fmul_rn(p, lg);
    }
    sred[t] = acc; __syncthreads();
    for (int s = 128; s > 0; s >>= 1) {
        if (t < s) sred[t] += sred[t + s];
        __syncthreads();
    }
    double H = sred[0];

    double lacc = 0.0;
    for (int k = t; k < QPARTS; k += 256) lacc += g_loss_part[k];
    __syncthreads();
    sred[t] = lacc; __syncthreads();
    for (int s = 128; s > 0; s >>= 1) {
        if (t < s) sred[t] += sred[t + s];
        __syncthreads();
    }
    if (t == 0) {
        float m    = (float)(sred[0] / (double)Q_ELEMS);
        float loss = __fadd_rn(m, __fmul_rn(0.25f, m));
        out[0] = loss;
        if (has_full) out[1 + Q_ELEMS] = expf(-(float)H);
    }
}

// ---------------------------------------------------------------------------
extern "C" void kernel_launch(void* const* d_in, const int* in_sizes, int n_in,
                              void* d_out, int out_size) {
    const float* x   = (const float*)d_in[0];
    const float* emb = (const float*)d_in[1];
    if (n_in >= 2 && in_sizes[0] == N_CODE * C_DIM && in_sizes[1] == Q_ELEMS) {
        const float* t = x; x = emb; emb = t;
    }
    float* out = (float*)d_out;

    long long enc_elems = (long long)out_size - ENC_OFF;
    int has_full = (enc_elems >= (long long)N_TOK * N_CODE);

    cudaFuncSetAttribute(k_mma, cudaFuncAttributeMaxDynamicSharedMemorySize,
                         SMEM_DYN);

    k_reset <<<32, 256>>>();
    k_cvt   <<<1024, 256>>>(emb);
    k_S     <<<N_TOK / 256, 256>>>(x);
    k_E2    <<<64, 128>>>(emb);
    k_mma   <<<N_TOK / 128, 384, SMEM_DYN>>>(x, out, has_full);
    k_refine<<<N_TOK / 8, 256>>>(x, emb);
    k_quant <<<QPARTS, 256>>>(x, emb, out + 1);
    if (!has_full && enc_elems > 0)
        cudaMemsetAsync(out + ENC_OFF, 0, (size_t)enc_elems * sizeof(float), 0);
    if (enc_elems > 0)
        k_enc<<<N_TOK / 256, 256>>>(out, enc_elems);
    k_final <<<1, 256>>>(out, has_full);
}

// round 14
// speedup vs baseline: 6.7971x; 1.0353x over previous
#include <cuda_runtime.h>
#include <cuda_bf16.h>
#include <cstdint>

// ---------------------------------------------------------------------------
// VQ-VAE VectorQuantizer on GB300 (sm_103, no 'a' features available in PTX).
// bf16 mma.sync approx distances -> rigorous window candidate filter ->
// exact sequential fp32-FMA refine (bit-identical to XLA, rel_err=0.0).
// R14: R11 k_mma, but encodings zeroing spread through the PRODUCER warps'
// per-nt loop (64KB/nt, hidden in their barrier slack). R13's upfront burst
// placement serialized against the prologue and lost 33us; k_enc stays
// hot-element-only.
// ---------------------------------------------------------------------------

#define N_TOK   16384
#define N_CODE  8192
#define C_DIM   256
#define Q_ELEMS 4194304      // 16*256*32*32
#define ENC_OFF 4194306LL    // 1 + Q_ELEMS + 1
#define SLOT    32           // candidate slots per (token, lane-quad position)
#define QPARTS  512

__device__ float          g_S[N_TOK];
__device__ float          g_L1[N_TOK];
__device__ float          g_E2[N_CODE];
__device__ int            g_idx[N_TOK];
__device__ int            g_counts[N_CODE];
__device__ double         g_loss_part[QPARTS];
__device__ int            g_cand[N_TOK][4 * SLOT];
__device__ int            g_cnt4[N_TOK][4];
__device__ unsigned       g_maxe_bits;
__device__ __nv_bfloat16  g_embh[N_CODE * C_DIM];   // bf16 codebook (4MB)

__device__ __forceinline__ float f_inf() { return __int_as_float(0x7f800000); }

__device__ __forceinline__ uint32_t smem_u32(const void* p) {
    uint32_t a;
    asm("{ .reg .u64 t; cvta.to.shared.u64 t, %1; cvt.u32.u64 %0, t; }"
        : "=r"(a) : "l"(p));
    return a;
}
#define LDSM_X4(r0, r1, r2, r3, addr)                                          \
    asm volatile("ldmatrix.sync.aligned.m8n8.x4.shared.b16 {%0,%1,%2,%3}, [%4];" \
        : "=r"(r0), "=r"(r1), "=r"(r2), "=r"(r3) : "r"(addr))
#define MMA_BF16(c0, c1, c2, c3, a0, a1, a2, a3, b0, b1)                       \
    asm volatile("mma.sync.aligned.m16n8k16.row.col.f32.bf16.bf16.f32 "       \
        "{%0,%1,%2,%3},{%4,%5,%6,%7},{%8,%9},{%0,%1,%2,%3};"                  \
        : "+f"(c0), "+f"(c1), "+f"(c2), "+f"(c3)                               \
        : "r"(a0), "r"(a1), "r"(a2), "r"(a3), "r"(b0), "r"(b1))

// ---------------------------------------------------------------- reset ----
__global__ void k_reset() {
    int t = blockIdx.x * blockDim.x + threadIdx.x;
    if (t < N_CODE) g_counts[t] = 0;
    if (t == 0)     g_maxe_bits = 0;
}

// --------------------------------------- one-time emb -> bf16 conversion ----
__global__ void k_cvt(const float* __restrict__ emb) {
    int i = blockIdx.x * blockDim.x + threadIdx.x;   // 262144 threads, 8 vals ea
    const float4 v0 = *(const float4*)&emb[(size_t)i * 8];
    const float4 v1 = *(const float4*)&emb[(size_t)i * 8 + 4];
    __nv_bfloat162 h0 = __floats2bfloat162_rn(v0.x, v0.y);
    __nv_bfloat162 h1 = __floats2bfloat162_rn(v0.z, v0.w);
    __nv_bfloat162 h2 = __floats2bfloat162_rn(v1.x, v1.y);
    __nv_bfloat162 h3 = __floats2bfloat162_rn(v1.z, v1.w);
    uint4 pk;
    pk.x = *(uint32_t*)&h0; pk.y = *(uint32_t*)&h1;
    pk.z = *(uint32_t*)&h2; pk.w = *(uint32_t*)&h3;
    *(uint4*)&g_embh[(size_t)i * 8] = pk;
}

// ----------------------------------------------- S = sum(x*x), L1 = sum|x| --
__global__ void k_S(const float* __restrict__ x) {
    int n = blockIdx.x * blockDim.x + threadIdx.x;
    if (n >= N_TOK) return;
    int b = n >> 10, hw = n & 1023;
    const float* p = x + (size_t)b * 262144 + hw;
    float acc = 0.0f, l1 = 0.0f;
    for (int c = 0; c < C_DIM; c++) {
        float v = p[(size_t)c * 1024];
        acc = __fadd_rn(acc, __fmul_rn(v, v));
        l1 += fabsf(v);
    }
    g_S[n] = acc;
    g_L1[n] = l1;
}

// ----------------------------------------- E2 = sum(e*e), track max |e| ----
__global__ void k_E2(const float* __restrict__ emb) {
    int k = blockIdx.x * blockDim.x + threadIdx.x;
    if (k >= N_CODE) return;
    const float4* p = (const float4*)(emb + (size_t)k * C_DIM);
    float acc = 0.0f, mx = 0.0f;
#pragma unroll 8
    for (int c4 = 0; c4 < C_DIM / 4; c4++) {
        float4 v = __ldg(&p[c4]);
        acc = __fadd_rn(acc, __fmul_rn(v.x, v.x));
        acc = __fadd_rn(acc, __fmul_rn(v.y, v.y));
        acc = __fadd_rn(acc, __fmul_rn(v.z, v.z));
        acc = __fadd_rn(acc, __fmul_rn(v.w, v.w));
        mx = fmaxf(mx, fmaxf(fmaxf(fabsf(v.x), fabsf(v.y)),
                             fmaxf(fabsf(v.z), fabsf(v.w))));
    }
    g_E2[k] = acc;
    atomicMax(&g_maxe_bits, __float_as_uint(mx));   // positive: uint order == float order
}

// ----------------------- bf16 mma.sync approx distances + candidate filter --
// 384 threads: warps 0-7 = MMA+epilogue (consumers), warps 8-11 = E staging
// (producers; exactly 1 per SMSP). A resident in smem, E double-buffered.
// Producers also zero this CTA's encodings slice, 64KB per nt (hidden in
// their barrier slack).
#define RS      528              // padded row stride bytes (264 halves)
#define SM_E2S  0                // 2 x 128 f32
#define SM_A    1024             // 128 rows * 528B = 67584
#define SM_EB0  68608
#define SM_EB1  136192
#define SMEM_DYN 203776

__global__ void __launch_bounds__(384, 1)
k_mma(const float* __restrict__ x, float* __restrict__ out, int zero_enc) {
    extern __shared__ char sm[];
    float* e2s = (float*)(sm + SM_E2S);
    const uint32_t sb = smem_u32(sm);
    const uint32_t sA = sb + SM_A;

    const int tid = threadIdx.x, w = tid >> 5, lane = tid & 31;
    const int mbase = blockIdx.x * 128;
    const int b     = mbase >> 10;
    const int hw0   = mbase & 1023;
    const float* xb = x + (size_t)b * 262144 + hw0;

    // ---- stage A: 128 tokens x 256 c, bf16, padded rows (all 384 threads) --
    for (int i = tid; i < 128 * 32; i += 384) {
        int m = i & 127, c0 = (i >> 7) * 8;
        float v0 = xb[(size_t)(c0 + 0) * 1024 + m];
        float v1 = xb[(size_t)(c0 + 1) * 1024 + m];
        float v2 = xb[(size_t)(c0 + 2) * 1024 + m];
        float v3 = xb[(size_t)(c0 + 3) * 1024 + m];
        float v4 = xb[(size_t)(c0 + 4) * 1024 + m];
        float v5 = xb[(size_t)(c0 + 5) * 1024 + m];
        float v6 = xb[(size_t)(c0 + 6) * 1024 + m];
        float v7 = xb[(size_t)(c0 + 7) * 1024 + m];
        __nv_bfloat162 h0 = __floats2bfloat162_rn(v0, v1);
        __nv_bfloat162 h1 = __floats2bfloat162_rn(v2, v3);
        __nv_bfloat162 h2 = __floats2bfloat162_rn(v4, v5);
        __nv_bfloat162 h3 = __floats2bfloat162_rn(v6, v7);
        uint4 pk;
        pk.x = *(uint32_t*)&h0; pk.y = *(uint32_t*)&h1;
        pk.z = *(uint32_t*)&h2; pk.w = *(uint32_t*)&h3;
        *(uint4*)(sm + SM_A + m * RS + c0 * 2) = pk;
    }

    // ---- E tile copy from bf16 codebook (pure 16B moves) ----
    auto stage_E = [&](int nt, int buf, int t0, int nth) {
        const int kb = nt * 128;
        char* eb = sm + (buf ? SM_EB1 : SM_EB0);
        for (int i = t0; i < 4096; i += nth) {           // 128 rows x 32 chunks
            int row = i >> 5, c16 = (i & 31);
            uint4 v = *(const uint4*)&g_embh[(size_t)(kb + row) * 256 + c16 * 8];
            *(uint4*)(eb + row * RS + c16 * 16) = v;
        }
        for (int i = t0; i < 128; i += nth) e2s[buf * 128 + i] = g_E2[kb + i];
    };

    stage_E(0, 0, tid, 384);
    __syncthreads();

    if (w >= 8) {
        // ------------- producer warps: stage ahead + spread zeroing --------
        const int pt = tid - 256;                        // 0..127
        float2* zdst = (float2*)(out + ENC_OFF) + (size_t)blockIdx.x * 524288;
        const float2 z = make_float2(0.0f, 0.0f);
        for (int nt = 0; nt < 64; nt++) {
            if (nt + 1 < 64) stage_E(nt + 1, (nt + 1) & 1, pt, 128);
            if (zero_enc) {
                // 8192 float2 per nt: 64 per producer thread, fire-and-forget
                float2* zc = zdst + (size_t)nt * 8192;
#pragma unroll 8
                for (int i = pt; i < 8192; i += 128) zc[i] = z;
            }
            __syncthreads();
        }
        return;
    }

    // --------------------------------- consumer warps: MMA + filter --------
    // hoist A fragments: 16 k-steps x 4 regs
    uint32_t a[16][4];
    {
        uint32_t abase = sA + (uint32_t)(w * 16 + (lane & 15)) * RS + ((lane >> 4) & 1) * 16;
#pragma unroll
        for (int k = 0; k < 16; k++)
            LDSM_X4(a[k][0], a[k][1], a[k][2], a[k][3], abase + k * 32);
    }

    const int   tok0 = mbase + w * 16 + (lane >> 2);
    const int   tok1 = tok0 + 8;
    const int   sub  = (lane & 3) * SLOT;
    const float S0 = g_S[tok0], S1 = g_S[tok1];
    const float maxe = __uint_as_float(g_maxe_bits);
    const float W0 = __fmaf_rn(0.0313f * maxe, g_L1[tok0], 1.3e-4f);
    const float W1 = __fmaf_rn(0.0313f * maxe, g_L1[tok1], 1.3e-4f);
    float rm0 = f_inf(), rm1 = f_inf(), thr0 = f_inf(), thr1 = f_inf();
    int   c0n = 0, c1n = 0;

    for (int nt = 0; nt < 64; nt++) {
        const uint32_t eB = sb + ((nt & 1) ? SM_EB1 : SM_EB0);
        const float*   e2 = e2s + (nt & 1) * 128;
        const int      kb = nt * 128;
        const uint32_t bbase = eB + (uint32_t)(lane & 15) * RS + ((lane >> 4) & 1) * 16;

#pragma unroll 1
        for (int fq = 0; fq < 2; fq++) {
            float acc[4][8];
#pragma unroll
            for (int q = 0; q < 4; q++)
#pragma unroll
                for (int r = 0; r < 8; r++) acc[q][r] = 0.f;

            const uint32_t bq = bbase + (uint32_t)fq * (64 * RS);

            uint32_t bb[2][4][4];
#pragma unroll
            for (int q = 0; q < 4; q++)
                LDSM_X4(bb[0][q][0], bb[0][q][1], bb[0][q][2], bb[0][q][3],
                        bq + (uint32_t)q * (16 * RS));
#pragma unroll
            for (int k = 0; k < 16; k++) {
                const int p = k & 1;
                if (k < 15) {
#pragma unroll
                    for (int q = 0; q < 4; q++)
                        LDSM_X4(bb[p ^ 1][q][0], bb[p ^ 1][q][1],
                                bb[p ^ 1][q][2], bb[p ^ 1][q][3],
                                bq + (uint32_t)q * (16 * RS) + (k + 1) * 32);
                }
#pragma unroll
                for (int q = 0; q < 4; q++) {
                    MMA_BF16(acc[q][0], acc[q][1], acc[q][2], acc[q][3],
                             a[k][0], a[k][1], a[k][2], a[k][3],
                             bb[p][q][0], bb[p][q][2]);
                    MMA_BF16(acc[q][4], acc[q][5], acc[q][6], acc[q][7],
                             a[k][0], a[k][1], a[k][2], a[k][3],
                             bb[p][q][1], bb[p][q][3]);
                }
            }

            // epilogue: d = (S + E2) - 2*dot ; atomic-free candidate capture
#pragma unroll
            for (int q = 0; q < 4; q++) {
                const int fp = fq * 4 + q;
#pragma unroll
                for (int h = 0; h < 2; h++) {
                    const int   f   = fp * 2 + h;
                    const int   cA  = f * 8 + (lane & 3) * 2;
                    const float e2a = e2[cA], e2b = e2[cA + 1];
                    const int   colA = kb + cA, colB = colA + 1;
                    const float dotA0 = h ? acc[q][4] : acc[q][0];
                    const float dotB0 = h ? acc[q][5] : acc[q][1];
                    const float dotA1 = h ? acc[q][6] : acc[q][2];
                    const float dotB1 = h ? acc[q][7] : acc[q][3];
                    float dA0 = __fsub_rn(__fadd_rn(S0, e2a), __fmul_rn(2.0f, dotA0));
                    float dB0 = __fsub_rn(__fadd_rn(S0, e2b), __fmul_rn(2.0f, dotB0));
                    float dA1 = __fsub_rn(__fadd_rn(S1, e2a), __fmul_rn(2.0f, dotA1));
                    float dB1 = __fsub_rn(__fadd_rn(S1, e2b), __fmul_rn(2.0f, dotB1));
                    if (dA0 < thr0) {
                        if (c0n < SLOT) g_cand[tok0][sub + c0n] = colA;
                        c0n++;
                        if (dA0 < rm0) { rm0 = dA0; thr0 = __fadd_rn(dA0, W0); }
                    }
                    if (dB0 < thr0) {
                        if (c0n < SLOT) g_cand[tok0][sub + c0n] = colB;
                        c0n++;
                        if (dB0 < rm0) { rm0 = dB0; thr0 = __fadd_rn(dB0, W0); }
                    }
                    if (dA1 < thr1) {
                        if (c1n < SLOT) g_cand[tok1][sub + c1n] = colA;
                        c1n++;
                        if (dA1 < rm1) { rm1 = dA1; thr1 = __fadd_rn(dA1, W1); }
                    }
                    if (dB1 < thr1) {
                        if (c1n < SLOT) g_cand[tok1][sub + c1n] = colB;
                        c1n++;
                        if (dB1 < rm1) { rm1 = dB1; thr1 = __fadd_rn(dB1, W1); }
                    }
                }
            }
            // tighten thresholds across the 4 lanes sharing the token rows
#pragma unroll
            for (int off = 1; off < 4; off <<= 1) {
                rm0 = fminf(rm0, __shfl_xor_sync(0xffffffff, rm0, off));
                rm1 = fminf(rm1, __shfl_xor_sync(0xffffffff, rm1, off));
            }
            thr0 = __fadd_rn(rm0, W0);
            thr1 = __fadd_rn(rm1, W1);
        }
        __syncthreads();
    }

    g_cnt4[tok0][lane & 3] = c0n;
    g_cnt4[tok1][lane & 3] = c1n;
}

// ------------------------------------- exact refinement (bit-exact argmin) --
__global__ void k_refine(const float* __restrict__ x, const float* __restrict__ emb) {
    __shared__ float xs[8][256];
    const int w = threadIdx.x >> 5, lane = threadIdx.x & 31;
    const int n = blockIdx.x * 8 + w;
    const int b = n >> 10, hw = n & 1023;
    const float* xb = x + (size_t)b * 262144 + hw;
    for (int c = lane; c < 256; c += 32) xs[w][c] = xb[(size_t)c * 1024];
    __syncwarp();

    const float S = g_S[n];
    int c4[4];
    c4[0] = g_cnt4[n][0]; c4[1] = g_cnt4[n][1];
    c4[2] = g_cnt4[n][2]; c4[3] = g_cnt4[n][3];
    const bool ovf = (c4[0] > SLOT) | (c4[1] > SLOT) | (c4[2] > SLOT) | (c4[3] > SLOT);
    const int total = c4[0] + c4[1] + c4[2] + c4[3];
    float bd = f_inf(); int bi = 0x7fffffff;

    auto exact_d = [&](int k) -> float {
        const float4* e = (const float4*)(emb + (size_t)k * 256);
        const float4* xv4 = (const float4*)xs[w];
        float acc = 0.0f;
#pragma unroll 8
        for (int c4i = 0; c4i < 64; c4i++) {
            float4 ev = __ldg(&e[c4i]);
            float4 xv = xv4[c4i];
            acc = __fmaf_rn(xv.x, ev.x, acc);
            acc = __fmaf_rn(xv.y, ev.y, acc);
            acc = __fmaf_rn(xv.z, ev.z, acc);
            acc = __fmaf_rn(xv.w, ev.w, acc);
        }
        float t = __fadd_rn(S, g_E2[k]);
        return __fsub_rn(t, __fmul_rn(2.0f, acc));
    };

    if (ovf) {                                          // overflow: full scan
        for (int k = lane; k < N_CODE; k += 32) {
            float d = exact_d(k);
            if (d < bd || (d == bd && k < bi)) { bd = d; bi = k; }
        }
    } else {
        for (int ci = lane; ci < total; ci += 32) {
            int r = ci, p = 0;
            while (r >= c4[p]) { r -= c4[p]; p++; }
            int k = g_cand[n][p * SLOT + r];
            float d = exact_d(k);
            if (d < bd || (d == bd && k < bi)) { bd = d; bi = k; }
        }
    }
#pragma unroll
    for (int off = 16; off > 0; off >>= 1) {
        float od = __shfl_down_sync(0xffffffff, bd, off);
        int   oi = __shfl_down_sync(0xffffffff, bi, off);
        if (od < bd || (od == bd && oi < bi)) { bd = od; bi = oi; }
    }
    if (lane == 0) g_idx[n] = bi;
}

// ---------------- quantized output + loss partial (smem row-gather) ---------
__global__ void __launch_bounds__(256)
k_quant(const float* __restrict__ x, const float* __restrict__ emb,
        float* __restrict__ outq) {
    __shared__ float  er[32][257];
    __shared__ int    sidx[32];
    __shared__ double sred[256];
    const int tid = threadIdx.x;
    const int n0  = blockIdx.x * 32;
    const int b   = n0 >> 10;
    const int hw0 = n0 & 1023;

    if (tid < 32) sidx[tid] = g_idx[n0 + tid];
    __syncthreads();
    for (int i = tid; i < 32 * 64; i += 256) {          // float4 gather
        int row = i >> 6, c4i = i & 63;
        float4 v = __ldg((const float4*)&emb[(size_t)sidx[row] * 256 + c4i * 4]);
        er[row][c4i * 4 + 0] = v.x;
        er[row][c4i * 4 + 1] = v.y;
        er[row][c4i * 4 + 2] = v.z;
        er[row][c4i * 4 + 3] = v.w;
    }
    __syncthreads();

    const int hwl = tid & 31;
    double part = 0.0;
    for (int c = tid >> 5; c < 256; c += 8) {
        size_t l = (size_t)b * 262144 + (size_t)c * 1024 + hw0 + hwl;
        float xv   = x[l];
        float q    = er[hwl][c];
        float diff = __fsub_rn(q, xv);
        outq[l]    = __fadd_rn(xv, diff);               // straight-through
        part += (double)__fmul_rn(diff, diff);
    }

    sred[tid] = part;
    __syncthreads();
    for (int s = 128; s > 0; s >>= 1) {
        if (tid < s) sred[tid] += sred[tid + s];
        __syncthreads();
    }
    if (tid == 0) g_loss_part[blockIdx.x] = sred[0];
}

// ------------- hot-element one-hot scatter + histogram (zeroing in k_mma) ---
__global__ void k_enc(float* __restrict__ out, long long enc_elems) {
    int n = blockIdx.x * blockDim.x + threadIdx.x;
    if (n >= N_TOK) return;
    int idx = g_idx[n];
    long long off = (long long)n * N_CODE + idx;
    if (off < enc_elems) out[ENC_OFF + off] = 1.0f;
    atomicAdd(&g_counts[idx], 1);
}

// -------------------------------------------------- loss + perplexity -------
__global__ void k_final(float* __restrict__ out, int has_full) {
    __shared__ double sred[256];
    int t = threadIdx.x;
    double acc = 0.0;
    for (int k = t; k < N_CODE; k += 256) {
        float p  = (float)g_counts[k] * (1.0f / 16384.0f);
        float lg = logf(__fadd_rn(p, 1e-10f));
        acc += (double)__fmul_rn(p, lg);
    }
    sred[t] = acc; __syncthreads();
    for (int s = 128; s > 0; s >>= 1) {
        if (t < s) sred[t] += sred[t + s];
        __syncthreads();
    }
    double H = sred[0];

    double lacc = 0.0;
    for (int k = t; k < QPARTS; k += 256) lacc += g_loss_part[k];
    __syncthreads();
    sred[t] = lacc; __syncthreads();
    for (int s = 128; s > 0; s >>= 1) {
        if (t < s) sred[t] += sred[t + s];
        __syncthreads();
    }
    if (t == 0) {
        float m    = (float)(sred[0] / (double)Q_ELEMS);
        float loss = __fadd_rn(m, __fmul_rn(0.25f, m));
        out[0] = loss;
        if (has_full) out[1 + Q_ELEMS] = expf(-(float)H);
    }
}

// ---------------------------------------------------------------------------
extern "C" void kernel_launch(void* const* d_in, const int* in_sizes, int n_in,
                              void* d_out, int out_size) {
    const float* x   = (const float*)d_in[0];
    const float* emb = (const float*)d_in[1];
    if (n_in >= 2 && in_sizes[0] == N_CODE * C_DIM && in_sizes[1] == Q_ELEMS) {
        const float* t = x; x = emb; emb = t;
    }
    float* out = (float*)d_out;

    long long enc_elems = (long long)out_size - ENC_OFF;
    int has_full = (enc_elems >= (long long)N_TOK * N_CODE);

    cudaFuncSetAttribute(k_mma, cudaFuncAttributeMaxDynamicSharedMemorySize,
                         SMEM_DYN);

    k_reset <<<32, 256>>>();
    k_cvt   <<<1024, 256>>>(emb);
    k_S     <<<N_TOK / 256, 256>>>(x);
    k_E2    <<<64, 128>>>(emb);
    k_mma   <<<N_TOK / 128, 384, SMEM_DYN>>>(x, out, has_full);
    k_refine<<<N_TOK / 8, 256>>>(x, emb);
    k_quant <<<QPARTS, 256>>>(x, emb, out + 1);
    if (!has_full && enc_elems > 0)
        cudaMemsetAsync(out + ENC_OFF, 0, (size_t)enc_elems * sizeof(float), 0);
    if (enc_elems > 0)
        k_enc<<<N_TOK / 256, 256>>>(out, enc_elems);
    k_final <<<1, 256>>>(out, has_full);
}

// round 15
// speedup vs baseline: 6.8987x; 1.0149x over previous
#include <cuda_runtime.h>
#include <cuda_bf16.h>
#include <cstdint>

// ---------------------------------------------------------------------------
// VQ-VAE VectorQuantizer on GB300 (sm_103, no 'a' features available in PTX).
// bf16 mma.sync approx distances -> rigorous window candidate filter ->
// exact sequential fp32-FMA refine (bit-identical to XLA, rel_err=0.0).
// R15: revert to R11 (633us champion: k_mma without zeroing, fused
// zero+scatter k_enc). k_cvt merged into k_E2 so k_mma is the 4th launch
// (= the one ncu captures) and one launch is saved.
// ---------------------------------------------------------------------------

#define N_TOK   16384
#define N_CODE  8192
#define C_DIM   256
#define Q_ELEMS 4194304      // 16*256*32*32
#define ENC_OFF 4194306LL    // 1 + Q_ELEMS + 1
#define SLOT    32           // candidate slots per (token, lane-quad position)
#define QPARTS  512

__device__ float          g_S[N_TOK];
__device__ float          g_L1[N_TOK];
__device__ float          g_E2[N_CODE];
__device__ int            g_idx[N_TOK];
__device__ int            g_counts[N_CODE];
__device__ double         g_loss_part[QPARTS];
__device__ int            g_cand[N_TOK][4 * SLOT];
__device__ int            g_cnt4[N_TOK][4];
__device__ unsigned       g_maxe_bits;
__device__ __nv_bfloat16  g_embh[N_CODE * C_DIM];   // bf16 codebook (4MB)

__device__ __forceinline__ float f_inf() { return __int_as_float(0x7f800000); }

__device__ __forceinline__ uint32_t smem_u32(const void* p) {
    uint32_t a;
    asm("{ .reg .u64 t; cvta.to.shared.u64 t, %1; cvt.u32.u64 %0, t; }"
        : "=r"(a) : "l"(p));
    return a;
}
#define LDSM_X4(r0, r1, r2, r3, addr)                                          \
    asm volatile("ldmatrix.sync.aligned.m8n8.x4.shared.b16 {%0,%1,%2,%3}, [%4];" \
        : "=r"(r0), "=r"(r1), "=r"(r2), "=r"(r3) : "r"(addr))
#define MMA_BF16(c0, c1, c2, c3, a0, a1, a2, a3, b0, b1)                       \
    asm volatile("mma.sync.aligned.m16n8k16.row.col.f32.bf16.bf16.f32 "       \
        "{%0,%1,%2,%3},{%4,%5,%6,%7},{%8,%9},{%0,%1,%2,%3};"                  \
        : "+f"(c0), "+f"(c1), "+f"(c2), "+f"(c3)                               \
        : "r"(a0), "r"(a1), "r"(a2), "r"(a3), "r"(b0), "r"(b1))

// ---------------------------------------------------------------- reset ----
__global__ void k_reset() {
    int t = blockIdx.x * blockDim.x + threadIdx.x;
    if (t < N_CODE) g_counts[t] = 0;
    if (t == 0)     g_maxe_bits = 0;
}

// ----------------------------------------------- S = sum(x*x), L1 = sum|x| --
__global__ void k_S(const float* __restrict__ x) {
    int n = blockIdx.x * blockDim.x + threadIdx.x;
    if (n >= N_TOK) return;
    int b = n >> 10, hw = n & 1023;
    const float* p = x + (size_t)b * 262144 + hw;
    float acc = 0.0f, l1 = 0.0f;
    for (int c = 0; c < C_DIM; c++) {
        float v = p[(size_t)c * 1024];
        acc = __fadd_rn(acc, __fmul_rn(v, v));
        l1 += fabsf(v);
    }
    g_S[n] = acc;
    g_L1[n] = l1;
}

// ---------- E2 = sum(e*e), max|e|, AND bf16 codebook conversion (fused) -----
// float4 row loads; per-code E2 chain order unchanged. Each thread also
// writes its row's bf16 conversion to g_embh (replaces the old k_cvt).
__global__ void k_E2(const float* __restrict__ emb) {
    int k = blockIdx.x * blockDim.x + threadIdx.x;
    if (k >= N_CODE) return;
    const float4* p = (const float4*)(emb + (size_t)k * C_DIM);
    uint4* dsth = (uint4*)&g_embh[(size_t)k * C_DIM];
    float acc = 0.0f, mx = 0.0f;
#pragma unroll 4
    for (int c8 = 0; c8 < C_DIM / 8; c8++) {
        float4 v0 = __ldg(&p[c8 * 2]);
        float4 v1 = __ldg(&p[c8 * 2 + 1]);
        acc = __fadd_rn(acc, __fmul_rn(v0.x, v0.x));
        acc = __fadd_rn(acc, __fmul_rn(v0.y, v0.y));
        acc = __fadd_rn(acc, __fmul_rn(v0.z, v0.z));
        acc = __fadd_rn(acc, __fmul_rn(v0.w, v0.w));
        acc = __fadd_rn(acc, __fmul_rn(v1.x, v1.x));
        acc = __fadd_rn(acc, __fmul_rn(v1.y, v1.y));
        acc = __fadd_rn(acc, __fmul_rn(v1.z, v1.z));
        acc = __fadd_rn(acc, __fmul_rn(v1.w, v1.w));
        mx = fmaxf(mx, fmaxf(fmaxf(fabsf(v0.x), fabsf(v0.y)),
                             fmaxf(fabsf(v0.z), fabsf(v0.w))));
        mx = fmaxf(mx, fmaxf(fmaxf(fabsf(v1.x), fabsf(v1.y)),
                             fmaxf(fabsf(v1.z), fabsf(v1.w))));
        __nv_bfloat162 h0 = __floats2bfloat162_rn(v0.x, v0.y);
        __nv_bfloat162 h1 = __floats2bfloat162_rn(v0.z, v0.w);
        __nv_bfloat162 h2 = __floats2bfloat162_rn(v1.x, v1.y);
        __nv_bfloat162 h3 = __floats2bfloat162_rn(v1.z, v1.w);
        uint4 pk;
        pk.x = *(uint32_t*)&h0; pk.y = *(uint32_t*)&h1;
        pk.z = *(uint32_t*)&h2; pk.w = *(uint32_t*)&h3;
        dsth[c8] = pk;
    }
    g_E2[k] = acc;
    atomicMax(&g_maxe_bits, __float_as_uint(mx));   // positive: uint order == float order
}

// ----------------------- bf16 mma.sync approx distances + candidate filter --
// 384 threads: warps 0-7 = MMA+epilogue (consumers), warps 8-11 = E staging
// (producers; exactly 1 per SMSP). A resident in smem, E double-buffered.
#define RS      528              // padded row stride bytes (264 halves)
#define SM_E2S  0                // 2 x 128 f32
#define SM_A    1024             // 128 rows * 528B = 67584
#define SM_EB0  68608
#define SM_EB1  136192
#define SMEM_DYN 203776

__global__ void __launch_bounds__(384, 1)
k_mma(const float* __restrict__ x) {
    extern __shared__ char sm[];
    float* e2s = (float*)(sm + SM_E2S);
    const uint32_t sb = smem_u32(sm);
    const uint32_t sA = sb + SM_A;

    const int tid = threadIdx.x, w = tid >> 5, lane = tid & 31;
    const int mbase = blockIdx.x * 128;
    const int b     = mbase >> 10;
    const int hw0   = mbase & 1023;
    const float* xb = x + (size_t)b * 262144 + hw0;

    // ---- stage A: 128 tokens x 256 c, bf16, padded rows (all 384 threads) --
    for (int i = tid; i < 128 * 32; i += 384) {
        int m = i & 127, c0 = (i >> 7) * 8;
        float v0 = xb[(size_t)(c0 + 0) * 1024 + m];
        float v1 = xb[(size_t)(c0 + 1) * 1024 + m];
        float v2 = xb[(size_t)(c0 + 2) * 1024 + m];
        float v3 = xb[(size_t)(c0 + 3) * 1024 + m];
        float v4 = xb[(size_t)(c0 + 4) * 1024 + m];
        float v5 = xb[(size_t)(c0 + 5) * 1024 + m];
        float v6 = xb[(size_t)(c0 + 6) * 1024 + m];
        float v7 = xb[(size_t)(c0 + 7) * 1024 + m];
        __nv_bfloat162 h0 = __floats2bfloat162_rn(v0, v1);
        __nv_bfloat162 h1 = __floats2bfloat162_rn(v2, v3);
        __nv_bfloat162 h2 = __floats2bfloat162_rn(v4, v5);
        __nv_bfloat162 h3 = __floats2bfloat162_rn(v6, v7);
        uint4 pk;
        pk.x = *(uint32_t*)&h0; pk.y = *(uint32_t*)&h1;
        pk.z = *(uint32_t*)&h2; pk.w = *(uint32_t*)&h3;
        *(uint4*)(sm + SM_A + m * RS + c0 * 2) = pk;
    }

    // ---- E tile copy from bf16 codebook (pure 16B moves) ----
    auto stage_E = [&](int nt, int buf, int t0, int nth) {
        const int kb = nt * 128;
        char* eb = sm + (buf ? SM_EB1 : SM_EB0);
        for (int i = t0; i < 4096; i += nth) {           // 128 rows x 32 chunks
            int row = i >> 5, c16 = (i & 31);
            uint4 v = *(const uint4*)&g_embh[(size_t)(kb + row) * 256 + c16 * 8];
            *(uint4*)(eb + row * RS + c16 * 16) = v;
        }
        for (int i = t0; i < 128; i += nth) e2s[buf * 128 + i] = g_E2[kb + i];
    };

    stage_E(0, 0, tid, 384);
    __syncthreads();

    if (w >= 8) {
        // ----------------------------- producer warps: stage ahead ---------
        const int pt = tid - 256;                        // 0..127
        for (int nt = 0; nt < 64; nt++) {
            if (nt + 1 < 64) stage_E(nt + 1, (nt + 1) & 1, pt, 128);
            __syncthreads();
        }
        return;
    }

    // --------------------------------- consumer warps: MMA + filter --------
    // hoist A fragments: 16 k-steps x 4 regs
    uint32_t a[16][4];
    {
        uint32_t abase = sA + (uint32_t)(w * 16 + (lane & 15)) * RS + ((lane >> 4) & 1) * 16;
#pragma unroll
        for (int k = 0; k < 16; k++)
            LDSM_X4(a[k][0], a[k][1], a[k][2], a[k][3], abase + k * 32);
    }

    const int   tok0 = mbase + w * 16 + (lane >> 2);
    const int   tok1 = tok0 + 8;
    const int   sub  = (lane & 3) * SLOT;
    const float S0 = g_S[tok0], S1 = g_S[tok1];
    const float maxe = __uint_as_float(g_maxe_bits);
    const float W0 = __fmaf_rn(0.0313f * maxe, g_L1[tok0], 1.3e-4f);
    const float W1 = __fmaf_rn(0.0313f * maxe, g_L1[tok1], 1.3e-4f);
    float rm0 = f_inf(), rm1 = f_inf(), thr0 = f_inf(), thr1 = f_inf();
    int   c0n = 0, c1n = 0;

    for (int nt = 0; nt < 64; nt++) {
        const uint32_t eB = sb + ((nt & 1) ? SM_EB1 : SM_EB0);
        const float*   e2 = e2s + (nt & 1) * 128;
        const int      kb = nt * 128;
        const uint32_t bbase = eB + (uint32_t)(lane & 15) * RS + ((lane >> 4) & 1) * 16;

#pragma unroll 1
        for (int fq = 0; fq < 2; fq++) {
            float acc[4][8];
#pragma unroll
            for (int q = 0; q < 4; q++)
#pragma unroll
                for (int r = 0; r < 8; r++) acc[q][r] = 0.f;

            const uint32_t bq = bbase + (uint32_t)fq * (64 * RS);

            uint32_t bb[2][4][4];
#pragma unroll
            for (int q = 0; q < 4; q++)
                LDSM_X4(bb[0][q][0], bb[0][q][1], bb[0][q][2], bb[0][q][3],
                        bq + (uint32_t)q * (16 * RS));
#pragma unroll
            for (int k = 0; k < 16; k++) {
                const int p = k & 1;
                if (k < 15) {
#pragma unroll
                    for (int q = 0; q < 4; q++)
                        LDSM_X4(bb[p ^ 1][q][0], bb[p ^ 1][q][1],
                                bb[p ^ 1][q][2], bb[p ^ 1][q][3],
                                bq + (uint32_t)q * (16 * RS) + (k + 1) * 32);
                }
#pragma unroll
                for (int q = 0; q < 4; q++) {
                    MMA_BF16(acc[q][0], acc[q][1], acc[q][2], acc[q][3],
                             a[k][0], a[k][1], a[k][2], a[k][3],
                             bb[p][q][0], bb[p][q][2]);
                    MMA_BF16(acc[q][4], acc[q][5], acc[q][6], acc[q][7],
                             a[k][0], a[k][1], a[k][2], a[k][3],
                             bb[p][q][1], bb[p][q][3]);
                }
            }

            // epilogue: d = (S + E2) - 2*dot ; atomic-free candidate capture
#pragma unroll
            for (int q = 0; q < 4; q++) {
                const int fp = fq * 4 + q;
#pragma unroll
                for (int h = 0; h < 2; h++) {
                    const int   f   = fp * 2 + h;
                    const int   cA  = f * 8 + (lane & 3) * 2;
                    const float e2a = e2[cA], e2b = e2[cA + 1];
                    const int   colA = kb + cA, colB = colA + 1;
                    const float dotA0 = h ? acc[q][4] : acc[q][0];
                    const float dotB0 = h ? acc[q][5] : acc[q][1];
                    const float dotA1 = h ? acc[q][6] : acc[q][2];
                    const float dotB1 = h ? acc[q][7] : acc[q][3];
                    float dA0 = __fsub_rn(__fadd_rn(S0, e2a), __fmul_rn(2.0f, dotA0));
                    float dB0 = __fsub_rn(__fadd_rn(S0, e2b), __fmul_rn(2.0f, dotB0));
                    float dA1 = __fsub_rn(__fadd_rn(S1, e2a), __fmul_rn(2.0f, dotA1));
                    float dB1 = __fsub_rn(__fadd_rn(S1, e2b), __fmul_rn(2.0f, dotB1));
                    if (dA0 < thr0) {
                        if (c0n < SLOT) g_cand[tok0][sub + c0n] = colA;
                        c0n++;
                        if (dA0 < rm0) { rm0 = dA0; thr0 = __fadd_rn(dA0, W0); }
                    }
                    if (dB0 < thr0) {
                        if (c0n < SLOT) g_cand[tok0][sub + c0n] = colB;
                        c0n++;
                        if (dB0 < rm0) { rm0 = dB0; thr0 = __fadd_rn(dB0, W0); }
                    }
                    if (dA1 < thr1) {
                        if (c1n < SLOT) g_cand[tok1][sub + c1n] = colA;
                        c1n++;
                        if (dA1 < rm1) { rm1 = dA1; thr1 = __fadd_rn(dA1, W1); }
                    }
                    if (dB1 < thr1) {
                        if (c1n < SLOT) g_cand[tok1][sub + c1n] = colB;
                        c1n++;
                        if (dB1 < rm1) { rm1 = dB1; thr1 = __fadd_rn(dB1, W1); }
                    }
                }
            }
            // tighten thresholds across the 4 lanes sharing the token rows
#pragma unroll
            for (int off = 1; off < 4; off <<= 1) {
                rm0 = fminf(rm0, __shfl_xor_sync(0xffffffff, rm0, off));
                rm1 = fminf(rm1, __shfl_xor_sync(0xffffffff, rm1, off));
            }
            thr0 = __fadd_rn(rm0, W0);
            thr1 = __fadd_rn(rm1, W1);
        }
        __syncthreads();
    }

    g_cnt4[tok0][lane & 3] = c0n;
    g_cnt4[tok1][lane & 3] = c1n;
}

// ------------------------------------- exact refinement (bit-exact argmin) --
__global__ void k_refine(const float* __restrict__ x, const float* __restrict__ emb) {
    __shared__ float xs[8][256];
    const int w = threadIdx.x >> 5, lane = threadIdx.x & 31;
    const int n = blockIdx.x * 8 + w;
    const int b = n >> 10, hw = n & 1023;
    const float* xb = x + (size_t)b * 262144 + hw;
    for (int c = lane; c < 256; c += 32) xs[w][c] = xb[(size_t)c * 1024];
    __syncwarp();

    const float S = g_S[n];
    int c4[4];
    c4[0] = g_cnt4[n][0]; c4[1] = g_cnt4[n][1];
    c4[2] = g_cnt4[n][2]; c4[3] = g_cnt4[n][3];
    const bool ovf = (c4[0] > SLOT) | (c4[1] > SLOT) | (c4[2] > SLOT) | (c4[3] > SLOT);
    const int total = c4[0] + c4[1] + c4[2] + c4[3];
    float bd = f_inf(); int bi = 0x7fffffff;

    auto exact_d = [&](int k) -> float {
        const float4* e = (const float4*)(emb + (size_t)k * 256);
        const float4* xv4 = (const float4*)xs[w];
        float acc = 0.0f;
#pragma unroll 8
        for (int c4i = 0; c4i < 64; c4i++) {
            float4 ev = __ldg(&e[c4i]);
            float4 xv = xv4[c4i];
            acc = __fmaf_rn(xv.x, ev.x, acc);
            acc = __fmaf_rn(xv.y, ev.y, acc);
            acc = __fmaf_rn(xv.z, ev.z, acc);
            acc = __fmaf_rn(xv.w, ev.w, acc);
        }
        float t = __fadd_rn(S, g_E2[k]);
        return __fsub_rn(t, __fmul_rn(2.0f, acc));
    };

    if (ovf) {                                          // overflow: full scan
        for (int k = lane; k < N_CODE; k += 32) {
            float d = exact_d(k);
            if (d < bd || (d == bd && k < bi)) { bd = d; bi = k; }
        }
    } else {
        for (int ci = lane; ci < total; ci += 32) {
            int r = ci, p = 0;
            while (r >= c4[p]) { r -= c4[p]; p++; }
            int k = g_cand[n][p * SLOT + r];
            float d = exact_d(k);
            if (d < bd || (d == bd && k < bi)) { bd = d; bi = k; }
        }
    }
#pragma unroll
    for (int off = 16; off > 0; off >>= 1) {
        float od = __shfl_down_sync(0xffffffff, bd, off);
        int   oi = __shfl_down_sync(0xffffffff, bi, off);
        if (od < bd || (od == bd && oi < bi)) { bd = od; bi = oi; }
    }
    if (lane == 0) g_idx[n] = bi;
}

// ---------------- quantized output + loss partial (smem row-gather) ---------
__global__ void __launch_bounds__(256)
k_quant(const float* __restrict__ x, const float* __restrict__ emb,
        float* __restrict__ outq) {
    __shared__ float  er[32][257];
    __shared__ int    sidx[32];
    __shared__ double sred[256];
    const int tid = threadIdx.x;
    const int n0  = blockIdx.x * 32;
    const int b   = n0 >> 10;
    const int hw0 = n0 & 1023;

    if (tid < 32) sidx[tid] = g_idx[n0 + tid];
    __syncthreads();
    for (int i = tid; i < 32 * 64; i += 256) {          // float4 gather
        int row = i >> 6, c4i = i & 63;
        float4 v = __ldg((const float4*)&emb[(size_t)sidx[row] * 256 + c4i * 4]);
        er[row][c4i * 4 + 0] = v.x;
        er[row][c4i * 4 + 1] = v.y;
        er[row][c4i * 4 + 2] = v.z;
        er[row][c4i * 4 + 3] = v.w;
    }
    __syncthreads();

    const int hwl = tid & 31;
    double part = 0.0;
    for (int c = tid >> 5; c < 256; c += 8) {
        size_t l = (size_t)b * 262144 + (size_t)c * 1024 + hw0 + hwl;
        float xv   = x[l];
        float q    = er[hwl][c];
        float diff = __fsub_rn(q, xv);
        outq[l]    = __fadd_rn(xv, diff);               // straight-through
        part += (double)__fmul_rn(diff, diff);
    }

    sred[tid] = part;
    __syncthreads();
    for (int s = 128; s > 0; s >>= 1) {
        if (tid < s) sred[tid] += sred[tid + s];
        __syncthreads();
    }
    if (tid == 0) g_loss_part[blockIdx.x] = sred[0];
}

// --------------- fused encodings zero + one-hot scatter + histogram ---------
// One warp per token row: write all 8192 floats (zeros + single 1.0).
// ENC_OFF is only 8B-aligned -> float2 stores. (Dedicated DRAM-bound kernel:
// proven faster than fusing the zeroing into k_mma in R13/R14.)
__global__ void __launch_bounds__(256)
k_enc(float* __restrict__ out) {
    const int w    = threadIdx.x >> 5, lane = threadIdx.x & 31;
    const int row  = blockIdx.x * 8 + w;
    const int idx  = g_idx[row];
    float2* dst = (float2*)(out + ENC_OFF) + (size_t)row * 4096;
    const int hot = idx >> 1;
    const float2 z = make_float2(0.0f, 0.0f);
#pragma unroll 8
    for (int j = 0; j < 128; j++) {
        int pos = j * 32 + lane;
        float2 v = z;
        if (pos == hot) {                                // rare: once per warp
            if (idx & 1) v.y = 1.0f; else v.x = 1.0f;
        }
        dst[pos] = v;
    }
    if (lane == 0) atomicAdd(&g_counts[idx], 1);
}

// -------------------------------------------------- loss + perplexity -------
__global__ void k_final(float* __restrict__ out, int has_full) {
    __shared__ double sred[256];
    int t = threadIdx.x;
    double acc = 0.0;
    for (int k = t; k < N_CODE; k += 256) {
        float p  = (float)g_counts[k] * (1.0f / 16384.0f);
        float lg = logf(__fadd_rn(p, 1e-10f));
        acc += (double)__fmul_rn(p, lg);
    }
    sred[t] = acc; __syncthreads();
    for (int s = 128; s > 0; s >>= 1) {
        if (t < s) sred[t] += sred[t + s];
        __syncthreads();
    }
    double H = sred[0];

    double lacc = 0.0;
    for (int k = t; k < QPARTS; k += 256) lacc += g_loss_part[k];
    __syncthreads();
    sred[t] = lacc; __syncthreads();
    for (int s = 128; s > 0; s >>= 1) {
        if (t < s) sred[t] += sred[t + s];
        __syncthreads();
    }
    if (t == 0) {
        float m    = (float)(sred[0] / (double)Q_ELEMS);
        float loss = __fadd_rn(m, __fmul_rn(0.25f, m));
        out[0] = loss;
        if (has_full) out[1 + Q_ELEMS] = expf(-(float)H);
    }
}

// ---------------------------------------------------------------------------
extern "C" void kernel_launch(void* const* d_in, const int* in_sizes, int n_in,
                              void* d_out, int out_size) {
    const float* x   = (const float*)d_in[0];
    const float* emb = (const float*)d_in[1];
    if (n_in >= 2 && in_sizes[0] == N_CODE * C_DIM && in_sizes[1] == Q_ELEMS) {
        const float* t = x; x = emb; emb = t;
    }
    float* out = (float*)d_out;

    long long enc_elems = (long long)out_size - ENC_OFF;
    int has_full = (enc_elems >= (long long)N_TOK * N_CODE);

    cudaFuncSetAttribute(k_mma, cudaFuncAttributeMaxDynamicSharedMemorySize,
                         SMEM_DYN);

    k_reset <<<32, 256>>>();                        // launch 1
    k_S     <<<N_TOK / 256, 256>>>(x);              // launch 2
    k_E2    <<<64, 128>>>(emb);                     // launch 3 (E2 + cvt fused)
    k_mma   <<<N_TOK / 128, 384, SMEM_DYN>>>(x);    // launch 4 -> ncu capture
    k_refine<<<N_TOK / 8, 256>>>(x, emb);
    k_quant <<<QPARTS, 256>>>(x, emb, out + 1);
    if (has_full)
        k_enc<<<N_TOK / 8, 256>>>(out);
    else if (enc_elems > 0)
        cudaMemsetAsync(out + ENC_OFF, 0, (size_t)enc_elems * sizeof(float), 0);
    k_final <<<1, 256>>>(out, has_full);
}

// round 16
// speedup vs baseline: 7.0076x; 1.0158x over previous
#include <cuda_runtime.h>
#include <cuda_bf16.h>
#include <cstdint>

// ---------------------------------------------------------------------------
// VQ-VAE VectorQuantizer on GB300 (sm_103, no 'a' features available in PTX).
// bf16 mma.sync approx distances -> rigorous window candidate filter ->
// exact sequential fp32-FMA refine (bit-identical to XLA, rel_err=0.0).
// R16: epilogue rebuilt -- branchless distance+fmin-tree, single tile-min
// early-out per (fq, token); capture loop (identical semantics) only runs on
// the rare hit. Removes the 32-deep dependent FSETP chain that idled the
// tensor pipe. All other kernels = R15 (633us champion).
// ---------------------------------------------------------------------------

#define N_TOK   16384
#define N_CODE  8192
#define C_DIM   256
#define Q_ELEMS 4194304      // 16*256*32*32
#define ENC_OFF 4194306LL    // 1 + Q_ELEMS + 1
#define SLOT    32           // candidate slots per (token, lane-quad position)
#define QPARTS  512

__device__ float          g_S[N_TOK];
__device__ float          g_L1[N_TOK];
__device__ float          g_E2[N_CODE];
__device__ int            g_idx[N_TOK];
__device__ int            g_counts[N_CODE];
__device__ double         g_loss_part[QPARTS];
__device__ int            g_cand[N_TOK][4 * SLOT];
__device__ int            g_cnt4[N_TOK][4];
__device__ unsigned       g_maxe_bits;
__device__ __nv_bfloat16  g_embh[N_CODE * C_DIM];   // bf16 codebook (4MB)

__device__ __forceinline__ float f_inf() { return __int_as_float(0x7f800000); }

__device__ __forceinline__ uint32_t smem_u32(const void* p) {
    uint32_t a;
    asm("{ .reg .u64 t; cvta.to.shared.u64 t, %1; cvt.u32.u64 %0, t; }"
        : "=r"(a) : "l"(p));
    return a;
}
#define LDSM_X4(r0, r1, r2, r3, addr)                                          \
    asm volatile("ldmatrix.sync.aligned.m8n8.x4.shared.b16 {%0,%1,%2,%3}, [%4];" \
        : "=r"(r0), "=r"(r1), "=r"(r2), "=r"(r3) : "r"(addr))
#define MMA_BF16(c0, c1, c2, c3, a0, a1, a2, a3, b0, b1)                       \
    asm volatile("mma.sync.aligned.m16n8k16.row.col.f32.bf16.bf16.f32 "       \
        "{%0,%1,%2,%3},{%4,%5,%6,%7},{%8,%9},{%0,%1,%2,%3};"                  \
        : "+f"(c0), "+f"(c1), "+f"(c2), "+f"(c3)                               \
        : "r"(a0), "r"(a1), "r"(a2), "r"(a3), "r"(b0), "r"(b1))

// ---------------------------------------------------------------- reset ----
__global__ void k_reset() {
    int t = blockIdx.x * blockDim.x + threadIdx.x;
    if (t < N_CODE) g_counts[t] = 0;
    if (t == 0)     g_maxe_bits = 0;
}

// ----------------------------------------------- S = sum(x*x), L1 = sum|x| --
__global__ void k_S(const float* __restrict__ x) {
    int n = blockIdx.x * blockDim.x + threadIdx.x;
    if (n >= N_TOK) return;
    int b = n >> 10, hw = n & 1023;
    const float* p = x + (size_t)b * 262144 + hw;
    float acc = 0.0f, l1 = 0.0f;
    for (int c = 0; c < C_DIM; c++) {
        float v = p[(size_t)c * 1024];
        acc = __fadd_rn(acc, __fmul_rn(v, v));
        l1 += fabsf(v);
    }
    g_S[n] = acc;
    g_L1[n] = l1;
}

// ---------- E2 = sum(e*e), max|e|, AND bf16 codebook conversion (fused) -----
__global__ void k_E2(const float* __restrict__ emb) {
    int k = blockIdx.x * blockDim.x + threadIdx.x;
    if (k >= N_CODE) return;
    const float4* p = (const float4*)(emb + (size_t)k * C_DIM);
    uint4* dsth = (uint4*)&g_embh[(size_t)k * C_DIM];
    float acc = 0.0f, mx = 0.0f;
#pragma unroll 4
    for (int c8 = 0; c8 < C_DIM / 8; c8++) {
        float4 v0 = __ldg(&p[c8 * 2]);
        float4 v1 = __ldg(&p[c8 * 2 + 1]);
        acc = __fadd_rn(acc, __fmul_rn(v0.x, v0.x));
        acc = __fadd_rn(acc, __fmul_rn(v0.y, v0.y));
        acc = __fadd_rn(acc, __fmul_rn(v0.z, v0.z));
        acc = __fadd_rn(acc, __fmul_rn(v0.w, v0.w));
        acc = __fadd_rn(acc, __fmul_rn(v1.x, v1.x));
        acc = __fadd_rn(acc, __fmul_rn(v1.y, v1.y));
        acc = __fadd_rn(acc, __fmul_rn(v1.z, v1.z));
        acc = __fadd_rn(acc, __fmul_rn(v1.w, v1.w));
        mx = fmaxf(mx, fmaxf(fmaxf(fabsf(v0.x), fabsf(v0.y)),
                             fmaxf(fabsf(v0.z), fabsf(v0.w))));
        mx = fmaxf(mx, fmaxf(fmaxf(fabsf(v1.x), fabsf(v1.y)),
                             fmaxf(fabsf(v1.z), fabsf(v1.w))));
        __nv_bfloat162 h0 = __floats2bfloat162_rn(v0.x, v0.y);
        __nv_bfloat162 h1 = __floats2bfloat162_rn(v0.z, v0.w);
        __nv_bfloat162 h2 = __floats2bfloat162_rn(v1.x, v1.y);
        __nv_bfloat162 h3 = __floats2bfloat162_rn(v1.z, v1.w);
        uint4 pk;
        pk.x = *(uint32_t*)&h0; pk.y = *(uint32_t*)&h1;
        pk.z = *(uint32_t*)&h2; pk.w = *(uint32_t*)&h3;
        dsth[c8] = pk;
    }
    g_E2[k] = acc;
    atomicMax(&g_maxe_bits, __float_as_uint(mx));   // positive: uint order == float order
}

// ----------------------- bf16 mma.sync approx distances + candidate filter --
// 384 threads: warps 0-7 = MMA+epilogue (consumers), warps 8-11 = E staging
// (producers; exactly 1 per SMSP). A resident in smem, E double-buffered.
#define RS      528              // padded row stride bytes (264 halves)
#define SM_E2S  0                // 2 x 128 f32
#define SM_A    1024             // 128 rows * 528B = 67584
#define SM_EB0  68608
#define SM_EB1  136192
#define SMEM_DYN 203776

__global__ void __launch_bounds__(384, 1)
k_mma(const float* __restrict__ x) {
    extern __shared__ char sm[];
    float* e2s = (float*)(sm + SM_E2S);
    const uint32_t sb = smem_u32(sm);
    const uint32_t sA = sb + SM_A;

    const int tid = threadIdx.x, w = tid >> 5, lane = tid & 31;
    const int mbase = blockIdx.x * 128;
    const int b     = mbase >> 10;
    const int hw0   = mbase & 1023;
    const float* xb = x + (size_t)b * 262144 + hw0;

    // ---- stage A: 128 tokens x 256 c, bf16, padded rows (all 384 threads) --
    for (int i = tid; i < 128 * 32; i += 384) {
        int m = i & 127, c0 = (i >> 7) * 8;
        float v0 = xb[(size_t)(c0 + 0) * 1024 + m];
        float v1 = xb[(size_t)(c0 + 1) * 1024 + m];
        float v2 = xb[(size_t)(c0 + 2) * 1024 + m];
        float v3 = xb[(size_t)(c0 + 3) * 1024 + m];
        float v4 = xb[(size_t)(c0 + 4) * 1024 + m];
        float v5 = xb[(size_t)(c0 + 5) * 1024 + m];
        float v6 = xb[(size_t)(c0 + 6) * 1024 + m];
        float v7 = xb[(size_t)(c0 + 7) * 1024 + m];
        __nv_bfloat162 h0 = __floats2bfloat162_rn(v0, v1);
        __nv_bfloat162 h1 = __floats2bfloat162_rn(v2, v3);
        __nv_bfloat162 h2 = __floats2bfloat162_rn(v4, v5);
        __nv_bfloat162 h3 = __floats2bfloat162_rn(v6, v7);
        uint4 pk;
        pk.x = *(uint32_t*)&h0; pk.y = *(uint32_t*)&h1;
        pk.z = *(uint32_t*)&h2; pk.w = *(uint32_t*)&h3;
        *(uint4*)(sm + SM_A + m * RS + c0 * 2) = pk;
    }

    // ---- E tile copy from bf16 codebook (pure 16B moves) ----
    auto stage_E = [&](int nt, int buf, int t0, int nth) {
        const int kb = nt * 128;
        char* eb = sm + (buf ? SM_EB1 : SM_EB0);
        for (int i = t0; i < 4096; i += nth) {           // 128 rows x 32 chunks
            int row = i >> 5, c16 = (i & 31);
            uint4 v = *(const uint4*)&g_embh[(size_t)(kb + row) * 256 + c16 * 8];
            *(uint4*)(eb + row * RS + c16 * 16) = v;
        }
        for (int i = t0; i < 128; i += nth) e2s[buf * 128 + i] = g_E2[kb + i];
    };

    stage_E(0, 0, tid, 384);
    __syncthreads();

    if (w >= 8) {
        // ----------------------------- producer warps: stage ahead ---------
        const int pt = tid - 256;                        // 0..127
        for (int nt = 0; nt < 64; nt++) {
            if (nt + 1 < 64) stage_E(nt + 1, (nt + 1) & 1, pt, 128);
            __syncthreads();
        }
        return;
    }

    // --------------------------------- consumer warps: MMA + filter --------
    // hoist A fragments: 16 k-steps x 4 regs
    uint32_t a[16][4];
    {
        uint32_t abase = sA + (uint32_t)(w * 16 + (lane & 15)) * RS + ((lane >> 4) & 1) * 16;
#pragma unroll
        for (int k = 0; k < 16; k++)
            LDSM_X4(a[k][0], a[k][1], a[k][2], a[k][3], abase + k * 32);
    }

    const int   tok0 = mbase + w * 16 + (lane >> 2);
    const int   tok1 = tok0 + 8;
    const int   sub  = (lane & 3) * SLOT;
    const float S0 = g_S[tok0], S1 = g_S[tok1];
    const float maxe = __uint_as_float(g_maxe_bits);
    const float W0 = __fmaf_rn(0.0313f * maxe, g_L1[tok0], 1.3e-4f);
    const float W1 = __fmaf_rn(0.0313f * maxe, g_L1[tok1], 1.3e-4f);
    float rm0 = f_inf(), rm1 = f_inf(), thr0 = f_inf(), thr1 = f_inf();
    int   c0n = 0, c1n = 0;

    for (int nt = 0; nt < 64; nt++) {
        const uint32_t eB = sb + ((nt & 1) ? SM_EB1 : SM_EB0);
        const float*   e2 = e2s + (nt & 1) * 128;
        const int      kb = nt * 128;
        const uint32_t bbase = eB + (uint32_t)(lane & 15) * RS + ((lane >> 4) & 1) * 16;

#pragma unroll 1
        for (int fq = 0; fq < 2; fq++) {
            float acc[4][8];
#pragma unroll
            for (int q = 0; q < 4; q++)
#pragma unroll
                for (int r = 0; r < 8; r++) acc[q][r] = 0.f;

            const uint32_t bq = bbase + (uint32_t)fq * (64 * RS);

            uint32_t bb[2][4][4];
#pragma unroll
            for (int q = 0; q < 4; q++)
                LDSM_X4(bb[0][q][0], bb[0][q][1], bb[0][q][2], bb[0][q][3],
                        bq + (uint32_t)q * (16 * RS));
#pragma unroll
            for (int k = 0; k < 16; k++) {
                const int p = k & 1;
                if (k < 15) {
#pragma unroll
                    for (int q = 0; q < 4; q++)
                        LDSM_X4(bb[p ^ 1][q][0], bb[p ^ 1][q][1],
                                bb[p ^ 1][q][2], bb[p ^ 1][q][3],
                                bq + (uint32_t)q * (16 * RS) + (k + 1) * 32);
                }
#pragma unroll
                for (int q = 0; q < 4; q++) {
                    MMA_BF16(acc[q][0], acc[q][1], acc[q][2], acc[q][3],
                             a[k][0], a[k][1], a[k][2], a[k][3],
                             bb[p][q][0], bb[p][q][2]);
                    MMA_BF16(acc[q][4], acc[q][5], acc[q][6], acc[q][7],
                             a[k][0], a[k][1], a[k][2], a[k][3],
                             bb[p][q][1], bb[p][q][3]);
                }
            }

            // ---- epilogue: branchless distances + fmin tree + early-out ----
            // d0/d1[s*2+{0,1}] = dists for slot s=(q*2+h), codes colA/colB.
            float d0[16], d1[16];
#pragma unroll
            for (int q = 0; q < 4; q++) {
#pragma unroll
                for (int h = 0; h < 2; h++) {
                    const int   s   = q * 2 + h;
                    const int   cA  = (fq * 8 + s) * 8 + (lane & 3) * 2;
                    const float e2a = e2[cA], e2b = e2[cA + 1];
                    const float dotA0 = h ? acc[q][4] : acc[q][0];
                    const float dotB0 = h ? acc[q][5] : acc[q][1];
                    const float dotA1 = h ? acc[q][6] : acc[q][2];
                    const float dotB1 = h ? acc[q][7] : acc[q][3];
                    d0[s * 2 + 0] = __fsub_rn(__fadd_rn(S0, e2a), __fmul_rn(2.0f, dotA0));
                    d0[s * 2 + 1] = __fsub_rn(__fadd_rn(S0, e2b), __fmul_rn(2.0f, dotB0));
                    d1[s * 2 + 0] = __fsub_rn(__fadd_rn(S1, e2a), __fmul_rn(2.0f, dotA1));
                    d1[s * 2 + 1] = __fsub_rn(__fadd_rn(S1, e2b), __fmul_rn(2.0f, dotB1));
                }
            }
            // fmin trees (branchless, fma pipe)
            float m0 = d0[0], m1 = d1[0];
#pragma unroll
            for (int i = 1; i < 16; i++) {
                m0 = fminf(m0, d0[i]);
                m1 = fminf(m1, d1[i]);
            }
            // rare-hit capture: semantics identical to the sequential scan
            // (skip is safe: m >= thr => every d >= thr => no capture/update)
            if (m0 < thr0) {
#pragma unroll
                for (int s = 0; s < 8; s++) {
                    const int colA = kb + (fq * 8 + s) * 8 + (lane & 3) * 2;
                    float dA = d0[s * 2], dB = d0[s * 2 + 1];
                    if (dA < thr0) {
                        if (c0n < SLOT) g_cand[tok0][sub + c0n] = colA;
                        c0n++;
                        if (dA < rm0) { rm0 = dA; thr0 = __fadd_rn(dA, W0); }
                    }
                    if (dB < thr0) {
                        if (c0n < SLOT) g_cand[tok0][sub + c0n] = colA + 1;
                        c0n++;
                        if (dB < rm0) { rm0 = dB; thr0 = __fadd_rn(dB, W0); }
                    }
                }
            }
            if (m1 < thr1) {
#pragma unroll
                for (int s = 0; s < 8; s++) {
                    const int colA = kb + (fq * 8 + s) * 8 + (lane & 3) * 2;
                    float dA = d1[s * 2], dB = d1[s * 2 + 1];
                    if (dA < thr1) {
                        if (c1n < SLOT) g_cand[tok1][sub + c1n] = colA;
                        c1n++;
                        if (dA < rm1) { rm1 = dA; thr1 = __fadd_rn(dA, W1); }
                    }
                    if (dB < thr1) {
                        if (c1n < SLOT) g_cand[tok1][sub + c1n] = colA + 1;
                        c1n++;
                        if (dB < rm1) { rm1 = dB; thr1 = __fadd_rn(dB, W1); }
                    }
                }
            }
            // tighten thresholds across the 4 lanes sharing the token rows
#pragma unroll
            for (int off = 1; off < 4; off <<= 1) {
                rm0 = fminf(rm0, __shfl_xor_sync(0xffffffff, rm0, off));
                rm1 = fminf(rm1, __shfl_xor_sync(0xffffffff, rm1, off));
            }
            thr0 = __fadd_rn(rm0, W0);
            thr1 = __fadd_rn(rm1, W1);
        }
        __syncthreads();
    }

    g_cnt4[tok0][lane & 3] = c0n;
    g_cnt4[tok1][lane & 3] = c1n;
}

// ------------------------------------- exact refinement (bit-exact argmin) --
__global__ void k_refine(const float* __restrict__ x, const float* __restrict__ emb) {
    __shared__ float xs[8][256];
    const int w = threadIdx.x >> 5, lane = threadIdx.x & 31;
    const int n = blockIdx.x * 8 + w;
    const int b = n >> 10, hw = n & 1023;
    const float* xb = x + (size_t)b * 262144 + hw;
    for (int c = lane; c < 256; c += 32) xs[w][c] = xb[(size_t)c * 1024];
    __syncwarp();

    const float S = g_S[n];
    int c4[4];
    c4[0] = g_cnt4[n][0]; c4[1] = g_cnt4[n][1];
    c4[2] = g_cnt4[n][2]; c4[3] = g_cnt4[n][3];
    const bool ovf = (c4[0] > SLOT) | (c4[1] > SLOT) | (c4[2] > SLOT) | (c4[3] > SLOT);
    const int total = c4[0] + c4[1] + c4[2] + c4[3];
    float bd = f_inf(); int bi = 0x7fffffff;

    auto exact_d = [&](int k) -> float {
        const float4* e = (const float4*)(emb + (size_t)k * 256);
        const float4* xv4 = (const float4*)xs[w];
        float acc = 0.0f;
#pragma unroll 8
        for (int c4i = 0; c4i < 64; c4i++) {
            float4 ev = __ldg(&e[c4i]);
            float4 xv = xv4[c4i];
            acc = __fmaf_rn(xv.x, ev.x, acc);
            acc = __fmaf_rn(xv.y, ev.y, acc);
            acc = __fmaf_rn(xv.z, ev.z, acc);
            acc = __fmaf_rn(xv.w, ev.w, acc);
        }
        float t = __fadd_rn(S, g_E2[k]);
        return __fsub_rn(t, __fmul_rn(2.0f, acc));
    };

    if (ovf) {                                          // overflow: full scan
        for (int k = lane; k < N_CODE; k += 32) {
            float d = exact_d(k);
            if (d < bd || (d == bd && k < bi)) { bd = d; bi = k; }
        }
    } else {
        for (int ci = lane; ci < total; ci += 32) {
            int r = ci, p = 0;
            while (r >= c4[p]) { r -= c4[p]; p++; }
            int k = g_cand[n][p * SLOT + r];
            float d = exact_d(k);
            if (d < bd || (d == bd && k < bi)) { bd = d; bi = k; }
        }
    }
#pragma unroll
    for (int off = 16; off > 0; off >>= 1) {
        float od = __shfl_down_sync(0xffffffff, bd, off);
        int   oi = __shfl_down_sync(0xffffffff, bi, off);
        if (od < bd || (od == bd && oi < bi)) { bd = od; bi = oi; }
    }
    if (lane == 0) g_idx[n] = bi;
}

// ---------------- quantized output + loss partial (smem row-gather) ---------
__global__ void __launch_bounds__(256)
k_quant(const float* __restrict__ x, const float* __restrict__ emb,
        float* __restrict__ outq) {
    __shared__ float  er[32][257];
    __shared__ int    sidx[32];
    __shared__ double sred[256];
    const int tid = threadIdx.x;
    const int n0  = blockIdx.x * 32;
    const int b   = n0 >> 10;
    const int hw0 = n0 & 1023;

    if (tid < 32) sidx[tid] = g_idx[n0 + tid];
    __syncthreads();
    for (int i = tid; i < 32 * 64; i += 256) {          // float4 gather
        int row = i >> 6, c4i = i & 63;
        float4 v = __ldg((const float4*)&emb[(size_t)sidx[row] * 256 + c4i * 4]);
        er[row][c4i * 4 + 0] = v.x;
        er[row][c4i * 4 + 1] = v.y;
        er[row][c4i * 4 + 2] = v.z;
        er[row][c4i * 4 + 3] = v.w;
    }
    __syncthreads();

    const int hwl = tid & 31;
    double part = 0.0;
    for (int c = tid >> 5; c < 256; c += 8) {
        size_t l = (size_t)b * 262144 + (size_t)c * 1024 + hw0 + hwl;
        float xv   = x[l];
        float q    = er[hwl][c];
        float diff = __fsub_rn(q, xv);
        outq[l]    = __fadd_rn(xv, diff);               // straight-through
        part += (double)__fmul_rn(diff, diff);
    }

    sred[tid] = part;
    __syncthreads();
    for (int s = 128; s > 0; s >>= 1) {
        if (tid < s) sred[tid] += sred[tid + s];
        __syncthreads();
    }
    if (tid == 0) g_loss_part[blockIdx.x] = sred[0];
}

// --------------- fused encodings zero + one-hot scatter + histogram ---------
__global__ void __launch_bounds__(256)
k_enc(float* __restrict__ out) {
    const int w    = threadIdx.x >> 5, lane = threadIdx.x & 31;
    const int row  = blockIdx.x * 8 + w;
    const int idx  = g_idx[row];
    float2* dst = (float2*)(out + ENC_OFF) + (size_t)row * 4096;
    const int hot = idx >> 1;
    const float2 z = make_float2(0.0f, 0.0f);
#pragma unroll 8
    for (int j = 0; j < 128; j++) {
        int pos = j * 32 + lane;
        float2 v = z;
        if (pos == hot) {                                // rare: once per warp
            if (idx & 1) v.y = 1.0f; else v.x = 1.0f;
        }
        dst[pos] = v;
    }
    if (lane == 0) atomicAdd(&g_counts[idx], 1);
}

// -------------------------------------------------- loss + perplexity -------
__global__ void k_final(float* __restrict__ out, int has_full) {
    __shared__ double sred[256];
    int t = threadIdx.x;
    double acc = 0.0;
    for (int k = t; k < N_CODE; k += 256) {
        float p  = (float)g_counts[k] * (1.0f / 16384.0f);
        float lg = logf(__fadd_rn(p, 1e-10f));
        acc += (double)__fmul_rn(p, lg);
    }
    sred[t] = acc; __syncthreads();
    for (int s = 128; s > 0; s >>= 1) {
        if (t < s) sred[t] += sred[t + s];
        __syncthreads();
    }
    double H = sred[0];

    double lacc = 0.0;
    for (int k = t; k < QPARTS; k += 256) lacc += g_loss_part[k];
    __syncthreads();
    sred[t] = lacc; __syncthreads();
    for (int s = 128; s > 0; s >>= 1) {
        if (t < s) sred[t] += sred[t + s];
        __syncthreads();
    }
    if (t == 0) {
        float m    = (float)(sred[0] / (double)Q_ELEMS);
        float loss = __fadd_rn(m, __fmul_rn(0.25f, m));
        out[0] = loss;
        if (has_full) out[1 + Q_ELEMS] = expf(-(float)H);
    }
}

// ---------------------------------------------------------------------------
extern "C" void kernel_launch(void* const* d_in, const int* in_sizes, int n_in,
                              void* d_out, int out_size) {
    const float* x   = (const float*)d_in[0];
    const float* emb = (const float*)d_in[1];
    if (n_in >= 2 && in_sizes[0] == N_CODE * C_DIM && in_sizes[1] == Q_ELEMS) {
        const float* t = x; x = emb; emb = t;
    }
    float* out = (float*)d_out;

    long long enc_elems = (long long)out_size - ENC_OFF;
    int has_full = (enc_elems >= (long long)N_TOK * N_CODE);

    cudaFuncSetAttribute(k_mma, cudaFuncAttributeMaxDynamicSharedMemorySize,
                         SMEM_DYN);

    k_reset <<<32, 256>>>();                        // launch 1
    k_S     <<<N_TOK / 256, 256>>>(x);              // launch 2
    k_E2    <<<64, 128>>>(emb);                     // launch 3 (E2 + cvt fused)
    k_mma   <<<N_TOK / 128, 384, SMEM_DYN>>>(x);    // launch 4 -> ncu capture
    k_refine<<<N_TOK / 8, 256>>>(x, emb);
    k_quant <<<QPARTS, 256>>>(x, emb, out + 1);
    if (has_full)
        k_enc<<<N_TOK / 8, 256>>>(out);
    else if (enc_elems > 0)
        cudaMemsetAsync(out + ENC_OFF, 0, (size_t)enc_elems * sizeof(float), 0);
    k_final <<<1, 256>>>(out, has_full);
}

// round 17
// speedup vs baseline: 7.0894x; 1.0117x over previous
#include <cuda_runtime.h>
#include <cuda_bf16.h>
#include <cstdint>

// ---------------------------------------------------------------------------
// VQ-VAE VectorQuantizer on GB300 (sm_103, no 'a' features available in PTX).
// bf16 mma.sync approx distances -> rigorous window candidate filter ->
// exact sequential fp32-FMA refine (bit-identical to XLA, rel_err=0.0).
// R17: epilogue moved to max-dot domain (t = dot - e2/2; S cancels -> 1 op
// per element instead of 3) and overlapped with the next fq's HMMA chain
// (dual accumulators, single-buffered B frags to stay under the 170-reg cap).
// ---------------------------------------------------------------------------

#define N_TOK   16384
#define N_CODE  8192
#define C_DIM   256
#define Q_ELEMS 4194304      // 16*256*32*32
#define ENC_OFF 4194306LL    // 1 + Q_ELEMS + 1
#define SLOT    32           // candidate slots per (token, lane-quad position)
#define QPARTS  512

__device__ float          g_S[N_TOK];
__device__ float          g_L1[N_TOK];
__device__ float          g_E2[N_CODE];
__device__ int            g_idx[N_TOK];
__device__ int            g_counts[N_CODE];
__device__ double         g_loss_part[QPARTS];
__device__ int            g_cand[N_TOK][4 * SLOT];
__device__ int            g_cnt4[N_TOK][4];
__device__ unsigned       g_maxe_bits;
__device__ __nv_bfloat16  g_embh[N_CODE * C_DIM];   // bf16 codebook (4MB)

__device__ __forceinline__ float f_inf()  { return __int_as_float(0x7f800000); }
__device__ __forceinline__ float f_ninf() { return __int_as_float(0xff800000); }

__device__ __forceinline__ uint32_t smem_u32(const void* p) {
    uint32_t a;
    asm("{ .reg .u64 t; cvta.to.shared.u64 t, %1; cvt.u32.u64 %0, t; }"
        : "=r"(a) : "l"(p));
    return a;
}
#define LDSM_X4(r0, r1, r2, r3, addr)                                          \
    asm volatile("ldmatrix.sync.aligned.m8n8.x4.shared.b16 {%0,%1,%2,%3}, [%4];" \
        : "=r"(r0), "=r"(r1), "=r"(r2), "=r"(r3) : "r"(addr))
#define MMA_BF16(c0, c1, c2, c3, a0, a1, a2, a3, b0, b1)                       \
    asm volatile("mma.sync.aligned.m16n8k16.row.col.f32.bf16.bf16.f32 "       \
        "{%0,%1,%2,%3},{%4,%5,%6,%7},{%8,%9},{%0,%1,%2,%3};"                  \
        : "+f"(c0), "+f"(c1), "+f"(c2), "+f"(c3)                               \
        : "r"(a0), "r"(a1), "r"(a2), "r"(a3), "r"(b0), "r"(b1))

// ---------------------------------------------------------------- reset ----
__global__ void k_reset() {
    int t = blockIdx.x * blockDim.x + threadIdx.x;
    if (t < N_CODE) g_counts[t] = 0;
    if (t == 0)     g_maxe_bits = 0;
}

// ----------------------------------------------- S = sum(x*x), L1 = sum|x| --
__global__ void k_S(const float* __restrict__ x) {
    int n = blockIdx.x * blockDim.x + threadIdx.x;
    if (n >= N_TOK) return;
    int b = n >> 10, hw = n & 1023;
    const float* p = x + (size_t)b * 262144 + hw;
    float acc = 0.0f, l1 = 0.0f;
    for (int c = 0; c < C_DIM; c++) {
        float v = p[(size_t)c * 1024];
        acc = __fadd_rn(acc, __fmul_rn(v, v));
        l1 += fabsf(v);
    }
    g_S[n] = acc;
    g_L1[n] = l1;
}

// ---------- E2 = sum(e*e), max|e|, AND bf16 codebook conversion (fused) -----
__global__ void k_E2(const float* __restrict__ emb) {
    int k = blockIdx.x * blockDim.x + threadIdx.x;
    if (k >= N_CODE) return;
    const float4* p = (const float4*)(emb + (size_t)k * C_DIM);
    uint4* dsth = (uint4*)&g_embh[(size_t)k * C_DIM];
    float acc = 0.0f, mx = 0.0f;
#pragma unroll 4
    for (int c8 = 0; c8 < C_DIM / 8; c8++) {
        float4 v0 = __ldg(&p[c8 * 2]);
        float4 v1 = __ldg(&p[c8 * 2 + 1]);
        acc = __fadd_rn(acc, __fmul_rn(v0.x, v0.x));
        acc = __fadd_rn(acc, __fmul_rn(v0.y, v0.y));
        acc = __fadd_rn(acc, __fmul_rn(v0.z, v0.z));
        acc = __fadd_rn(acc, __fmul_rn(v0.w, v0.w));
        acc = __fadd_rn(acc, __fmul_rn(v1.x, v1.x));
        acc = __fadd_rn(acc, __fmul_rn(v1.y, v1.y));
        acc = __fadd_rn(acc, __fmul_rn(v1.z, v1.z));
        acc = __fadd_rn(acc, __fmul_rn(v1.w, v1.w));
        mx = fmaxf(mx, fmaxf(fmaxf(fabsf(v0.x), fabsf(v0.y)),
                             fmaxf(fabsf(v0.z), fabsf(v0.w))));
        mx = fmaxf(mx, fmaxf(fmaxf(fabsf(v1.x), fabsf(v1.y)),
                             fmaxf(fabsf(v1.z), fabsf(v1.w))));
        __nv_bfloat162 h0 = __floats2bfloat162_rn(v0.x, v0.y);
        __nv_bfloat162 h1 = __floats2bfloat162_rn(v0.z, v0.w);
        __nv_bfloat162 h2 = __floats2bfloat162_rn(v1.x, v1.y);
        __nv_bfloat162 h3 = __floats2bfloat162_rn(v1.z, v1.w);
        uint4 pk;
        pk.x = *(uint32_t*)&h0; pk.y = *(uint32_t*)&h1;
        pk.z = *(uint32_t*)&h2; pk.w = *(uint32_t*)&h3;
        dsth[c8] = pk;
    }
    g_E2[k] = acc;
    atomicMax(&g_maxe_bits, __float_as_uint(mx));   // positive: uint order == float order
}

// ----------------------- bf16 mma.sync approx distances + candidate filter --
// 384 threads: warps 0-7 = MMA+epilogue (consumers), warps 8-11 = E staging
// (producers; exactly 1 per SMSP). A resident in smem, E double-buffered.
// Filter runs in the max-dot domain: t = dot - e2/2 (e2s stages e2*0.5).
#define RS      528              // padded row stride bytes (264 halves)
#define SM_E2S  0                // 2 x 128 f32 (pre-halved E2)
#define SM_A    1024             // 128 rows * 528B = 67584
#define SM_EB0  68608
#define SM_EB1  136192
#define SMEM_DYN 203776

__global__ void __launch_bounds__(384, 1)
k_mma(const float* __restrict__ x) {
    extern __shared__ char sm[];
    float* e2s = (float*)(sm + SM_E2S);
    const uint32_t sb = smem_u32(sm);
    const uint32_t sA = sb + SM_A;

    const int tid = threadIdx.x, w = tid >> 5, lane = tid & 31;
    const int mbase = blockIdx.x * 128;
    const int b     = mbase >> 10;
    const int hw0   = mbase & 1023;
    const float* xb = x + (size_t)b * 262144 + hw0;

    // ---- stage A: 128 tokens x 256 c, bf16, padded rows (all 384 threads) --
    for (int i = tid; i < 128 * 32; i += 384) {
        int m = i & 127, c0 = (i >> 7) * 8;
        float v0 = xb[(size_t)(c0 + 0) * 1024 + m];
        float v1 = xb[(size_t)(c0 + 1) * 1024 + m];
        float v2 = xb[(size_t)(c0 + 2) * 1024 + m];
        float v3 = xb[(size_t)(c0 + 3) * 1024 + m];
        float v4 = xb[(size_t)(c0 + 4) * 1024 + m];
        float v5 = xb[(size_t)(c0 + 5) * 1024 + m];
        float v6 = xb[(size_t)(c0 + 6) * 1024 + m];
        float v7 = xb[(size_t)(c0 + 7) * 1024 + m];
        __nv_bfloat162 h0 = __floats2bfloat162_rn(v0, v1);
        __nv_bfloat162 h1 = __floats2bfloat162_rn(v2, v3);
        __nv_bfloat162 h2 = __floats2bfloat162_rn(v4, v5);
        __nv_bfloat162 h3 = __floats2bfloat162_rn(v6, v7);
        uint4 pk;
        pk.x = *(uint32_t*)&h0; pk.y = *(uint32_t*)&h1;
        pk.z = *(uint32_t*)&h2; pk.w = *(uint32_t*)&h3;
        *(uint4*)(sm + SM_A + m * RS + c0 * 2) = pk;
    }

    // ---- E tile copy from bf16 codebook (pure 16B moves); e2s = E2 * 0.5 ---
    auto stage_E = [&](int nt, int buf, int t0, int nth) {
        const int kb = nt * 128;
        char* eb = sm + (buf ? SM_EB1 : SM_EB0);
        for (int i = t0; i < 4096; i += nth) {           // 128 rows x 32 chunks
            int row = i >> 5, c16 = (i & 31);
            uint4 v = *(const uint4*)&g_embh[(size_t)(kb + row) * 256 + c16 * 8];
            *(uint4*)(eb + row * RS + c16 * 16) = v;
        }
        for (int i = t0; i < 128; i += nth)
            e2s[buf * 128 + i] = 0.5f * g_E2[kb + i];    // exact scaling
    };

    stage_E(0, 0, tid, 384);
    __syncthreads();

    if (w >= 8) {
        // ----------------------------- producer warps: stage ahead ---------
        const int pt = tid - 256;                        // 0..127
        for (int nt = 0; nt < 64; nt++) {
            if (nt + 1 < 64) stage_E(nt + 1, (nt + 1) & 1, pt, 128);
            __syncthreads();
        }
        return;
    }

    // --------------------------------- consumer warps: MMA + filter --------
    // hoist A fragments: 16 k-steps x 4 regs
    uint32_t a[16][4];
    {
        uint32_t abase = sA + (uint32_t)(w * 16 + (lane & 15)) * RS + ((lane >> 4) & 1) * 16;
#pragma unroll
        for (int k = 0; k < 16; k++)
            LDSM_X4(a[k][0], a[k][1], a[k][2], a[k][3], abase + k * 32);
    }

    const int   tok0 = mbase + w * 16 + (lane >> 2);
    const int   tok1 = tok0 + 8;
    const int   sub  = (lane & 3) * SLOT;
    const float maxe = __uint_as_float(g_maxe_bits);
    // max-dot-domain window: W2 = 2*Delta_dot + slop (values ~1, slop tiny)
    const float W0 = __fmaf_rn(0.01565f * maxe, g_L1[tok0], 1e-5f);
    const float W1 = __fmaf_rn(0.01565f * maxe, g_L1[tok1], 1e-5f);
    float rm0 = f_ninf(), rm1 = f_ninf(), thr0 = f_ninf(), thr1 = f_ninf();
    int   c0n = 0, c1n = 0;

    for (int nt = 0; nt < 64; nt++) {
        const uint32_t eB = sb + ((nt & 1) ? SM_EB1 : SM_EB0);
        const float*   e2h = e2s + (nt & 1) * 128;
        const int      kb = nt * 128;
        const uint32_t bbase = eB + (uint32_t)(lane & 15) * RS + ((lane >> 4) & 1) * 16;

        float acc0[4][8], acc1[4][8];
#pragma unroll
        for (int q = 0; q < 4; q++)
#pragma unroll
            for (int r = 0; r < 8; r++) { acc0[q][r] = 0.f; acc1[q][r] = 0.f; }

        uint32_t bb[4][4];

        // ---- fq = 0 MMA ----
#pragma unroll
        for (int k = 0; k < 16; k++) {
#pragma unroll
            for (int q = 0; q < 4; q++)
                LDSM_X4(bb[q][0], bb[q][1], bb[q][2], bb[q][3],
                        bbase + (uint32_t)q * (16 * RS) + k * 32);
#pragma unroll
            for (int q = 0; q < 4; q++) {
                MMA_BF16(acc0[q][0], acc0[q][1], acc0[q][2], acc0[q][3],
                         a[k][0], a[k][1], a[k][2], a[k][3], bb[q][0], bb[q][2]);
                MMA_BF16(acc0[q][4], acc0[q][5], acc0[q][6], acc0[q][7],
                         a[k][0], a[k][1], a[k][2], a[k][3], bb[q][1], bb[q][3]);
            }
        }

        // ---- fq = 1 MMA (epilogue of fq0 overlaps this tensor work) ----
        const uint32_t bq1 = bbase + (uint32_t)(64 * RS);
#pragma unroll
        for (int k = 0; k < 16; k++) {
#pragma unroll
            for (int q = 0; q < 4; q++)
                LDSM_X4(bb[q][0], bb[q][1], bb[q][2], bb[q][3],
                        bq1 + (uint32_t)q * (16 * RS) + k * 32);
#pragma unroll
            for (int q = 0; q < 4; q++) {
                MMA_BF16(acc1[q][0], acc1[q][1], acc1[q][2], acc1[q][3],
                         a[k][0], a[k][1], a[k][2], a[k][3], bb[q][0], bb[q][2]);
                MMA_BF16(acc1[q][4], acc1[q][5], acc1[q][6], acc1[q][7],
                         a[k][0], a[k][1], a[k][2], a[k][3], bb[q][1], bb[q][3]);
            }
        }

        // ---- epilogue (max-dot domain): t = dot - e2/2; capture t > thr ----
        auto epi = [&](float (&acc)[4][8], int fq) {
            float t0[16], t1[16];
#pragma unroll
            for (int q = 0; q < 4; q++) {
#pragma unroll
                for (int h = 0; h < 2; h++) {
                    const int   s  = q * 2 + h;
                    const int   cA = (fq * 8 + s) * 8 + (lane & 3) * 2;
                    const float ea = e2h[cA], eb2 = e2h[cA + 1];
                    t0[s * 2 + 0] = __fsub_rn(h ? acc[q][4] : acc[q][0], ea);
                    t0[s * 2 + 1] = __fsub_rn(h ? acc[q][5] : acc[q][1], eb2);
                    t1[s * 2 + 0] = __fsub_rn(h ? acc[q][6] : acc[q][2], ea);
                    t1[s * 2 + 1] = __fsub_rn(h ? acc[q][7] : acc[q][3], eb2);
                }
            }
            float m0 = t0[0], m1 = t1[0];
#pragma unroll
            for (int i = 1; i < 16; i++) {
                m0 = fmaxf(m0, t0[i]);
                m1 = fmaxf(m1, t1[i]);
            }
            if (m0 > thr0) {                   // rare after warmup
#pragma unroll
                for (int s = 0; s < 8; s++) {
                    const int colA = kb + (fq * 8 + s) * 8 + (lane & 3) * 2;
                    float dA = t0[s * 2], dB = t0[s * 2 + 1];
                    if (dA > thr0) {
                        if (c0n < SLOT) g_cand[tok0][sub + c0n] = colA;
                        c0n++;
                        if (dA > rm0) { rm0 = dA; thr0 = __fsub_rn(dA, W0); }
                    }
                    if (dB > thr0) {
                        if (c0n < SLOT) g_cand[tok0][sub + c0n] = colA + 1;
                        c0n++;
                        if (dB > rm0) { rm0 = dB; thr0 = __fsub_rn(dB, W0); }
                    }
                }
            }
            if (m1 > thr1) {
#pragma unroll
                for (int s = 0; s < 8; s++) {
                    const int colA = kb + (fq * 8 + s) * 8 + (lane & 3) * 2;
                    float dA = t1[s * 2], dB = t1[s * 2 + 1];
                    if (dA > thr1) {
                        if (c1n < SLOT) g_cand[tok1][sub + c1n] = colA;
                        c1n++;
                        if (dA > rm1) { rm1 = dA; thr1 = __fsub_rn(dA, W1); }
                    }
                    if (dB > thr1) {
                        if (c1n < SLOT) g_cand[tok1][sub + c1n] = colA + 1;
                        c1n++;
                        if (dB > rm1) { rm1 = dB; thr1 = __fsub_rn(dB, W1); }
                    }
                }
            }
            // tighten across the 4 lanes sharing the token rows
#pragma unroll
            for (int off = 1; off < 4; off <<= 1) {
                rm0 = fmaxf(rm0, __shfl_xor_sync(0xffffffff, rm0, off));
                rm1 = fmaxf(rm1, __shfl_xor_sync(0xffffffff, rm1, off));
            }
            thr0 = __fsub_rn(rm0, W0);
            thr1 = __fsub_rn(rm1, W1);
        };

        epi(acc0, 0);      // overlaps fq1 HMMA still in the tensor pipe
        epi(acc1, 1);

        __syncthreads();
    }

    g_cnt4[tok0][lane & 3] = c0n;
    g_cnt4[tok1][lane & 3] = c1n;
}

// ------------------------------------- exact refinement (bit-exact argmin) --
__global__ void k_refine(const float* __restrict__ x, const float* __restrict__ emb) {
    __shared__ float xs[8][256];
    const int w = threadIdx.x >> 5, lane = threadIdx.x & 31;
    const int n = blockIdx.x * 8 + w;
    const int b = n >> 10, hw = n & 1023;
    const float* xb = x + (size_t)b * 262144 + hw;
    for (int c = lane; c < 256; c += 32) xs[w][c] = xb[(size_t)c * 1024];
    __syncwarp();

    const float S = g_S[n];
    int c4[4];
    c4[0] = g_cnt4[n][0]; c4[1] = g_cnt4[n][1];
    c4[2] = g_cnt4[n][2]; c4[3] = g_cnt4[n][3];
    const bool ovf = (c4[0] > SLOT) | (c4[1] > SLOT) | (c4[2] > SLOT) | (c4[3] > SLOT);
    const int total = c4[0] + c4[1] + c4[2] + c4[3];
    float bd = f_inf(); int bi = 0x7fffffff;

    auto exact_d = [&](int k) -> float {
        const float4* e = (const float4*)(emb + (size_t)k * 256);
        const float4* xv4 = (const float4*)xs[w];
        float acc = 0.0f;
#pragma unroll 8
        for (int c4i = 0; c4i < 64; c4i++) {
            float4 ev = __ldg(&e[c4i]);
            float4 xv = xv4[c4i];
            acc = __fmaf_rn(xv.x, ev.x, acc);
            acc = __fmaf_rn(xv.y, ev.y, acc);
            acc = __fmaf_rn(xv.z, ev.z, acc);
            acc = __fmaf_rn(xv.w, ev.w, acc);
        }
        float t = __fadd_rn(S, g_E2[k]);
        return __fsub_rn(t, __fmul_rn(2.0f, acc));
    };

    if (ovf) {                                          // overflow: full scan
        for (int k = lane; k < N_CODE; k += 32) {
            float d = exact_d(k);
            if (d < bd || (d == bd && k < bi)) { bd = d; bi = k; }
        }
    } else {
        for (int ci = lane; ci < total; ci += 32) {
            int r = ci, p = 0;
            while (r >= c4[p]) { r -= c4[p]; p++; }
            int k = g_cand[n][p * SLOT + r];
            float d = exact_d(k);
            if (d < bd || (d == bd && k < bi)) { bd = d; bi = k; }
        }
    }
#pragma unroll
    for (int off = 16; off > 0; off >>= 1) {
        float od = __shfl_down_sync(0xffffffff, bd, off);
        int   oi = __shfl_down_sync(0xffffffff, bi, off);
        if (od < bd || (od == bd && oi < bi)) { bd = od; bi = oi; }
    }
    if (lane == 0) g_idx[n] = bi;
}

// ---------------- quantized output + loss partial (smem row-gather) ---------
__global__ void __launch_bounds__(256)
k_quant(const float* __restrict__ x, const float* __restrict__ emb,
        float* __restrict__ outq) {
    __shared__ float  er[32][257];
    __shared__ int    sidx[32];
    __shared__ double sred[256];
    const int tid = threadIdx.x;
    const int n0  = blockIdx.x * 32;
    const int b   = n0 >> 10;
    const int hw0 = n0 & 1023;

    if (tid < 32) sidx[tid] = g_idx[n0 + tid];
    __syncthreads();
    for (int i = tid; i < 32 * 64; i += 256) {          // float4 gather
        int row = i >> 6, c4i = i & 63;
        float4 v = __ldg((const float4*)&emb[(size_t)sidx[row] * 256 + c4i * 4]);
        er[row][c4i * 4 + 0] = v.x;
        er[row][c4i * 4 + 1] = v.y;
        er[row][c4i * 4 + 2] = v.z;
        er[row][c4i * 4 + 3] = v.w;
    }
    __syncthreads();

    const int hwl = tid & 31;
    double part = 0.0;
    for (int c = tid >> 5; c < 256; c += 8) {
        size_t l = (size_t)b * 262144 + (size_t)c * 1024 + hw0 + hwl;
        float xv   = x[l];
        float q    = er[hwl][c];
        float diff = __fsub_rn(q, xv);
        outq[l]    = __fadd_rn(xv, diff);               // straight-through
        part += (double)__fmul_rn(diff, diff);
    }

    sred[tid] = part;
    __syncthreads();
    for (int s = 128; s > 0; s >>= 1) {
        if (tid < s) sred[tid] += sred[tid + s];
        __syncthreads();
    }
    if (tid == 0) g_loss_part[blockIdx.x] = sred[0];
}

// --------------- fused encodings zero + one-hot scatter + histogram ---------
__global__ void __launch_bounds__(256)
k_enc(float* __restrict__ out) {
    const int w    = threadIdx.x >> 5, lane = threadIdx.x & 31;
    const int row  = blockIdx.x * 8 + w;
    const int idx  = g_idx[row];
    float2* dst = (float2*)(out + ENC_OFF) + (size_t)row * 4096;
    const int hot = idx >> 1;
    const float2 z = make_float2(0.0f, 0.0f);
#pragma unroll 8
    for (int j = 0; j < 128; j++) {
        int pos = j * 32 + lane;
        float2 v = z;
        if (pos == hot) {                                // rare: once per warp
            if (idx & 1) v.y = 1.0f; else v.x = 1.0f;
        }
        dst[pos] = v;
    }
    if (lane == 0) atomicAdd(&g_counts[idx], 1);
}

// -------------------------------------------------- loss + perplexity -------
__global__ void k_final(float* __restrict__ out, int has_full) {
    __shared__ double sred[256];
    int t = threadIdx.x;
    double acc = 0.0;
    for (int k = t; k < N_CODE; k += 256) {
        float p  = (float)g_counts[k] * (1.0f / 16384.0f);
        float lg = logf(__fadd_rn(p, 1e-10f));
        acc += (double)__fmul_rn(p, lg);
    }
    sred[t] = acc; __syncthreads();
    for (int s = 128; s > 0; s >>= 1) {
        if (t < s) sred[t] += sred[t + s];
        __syncthreads();
    }
    double H = sred[0];

    double lacc = 0.0;
    for (int k = t; k < QPARTS; k += 256) lacc += g_loss_part[k];
    __syncthreads();
    sred[t] = lacc; __syncthreads();
    for (int s = 128; s > 0; s >>= 1) {
        if (t < s) sred[t] += sred[t + s];
        __syncthreads();
    }
    if (t == 0) {
        float m    = (float)(sred[0] / (double)Q_ELEMS);
        float loss = __fadd_rn(m, __fmul_rn(0.25f, m));
        out[0] = loss;
        if (has_full) out[1 + Q_ELEMS] = expf(-(float)H);
    }
}

// ---------------------------------------------------------------------------
extern "C" void kernel_launch(void* const* d_in, const int* in_sizes, int n_in,
                              void* d_out, int out_size) {
    const float* x   = (const float*)d_in[0];
    const float* emb = (const float*)d_in[1];
    if (n_in >= 2 && in_sizes[0] == N_CODE * C_DIM && in_sizes[1] == Q_ELEMS) {
        const float* t = x; x = emb; emb = t;
    }
    float* out = (float*)d_out;

    long long enc_elems = (long long)out_size - ENC_OFF;
    int has_full = (enc_elems >= (long long)N_TOK * N_CODE);

    cudaFuncSetAttribute(k_mma, cudaFuncAttributeMaxDynamicSharedMemorySize,
                         SMEM_DYN);

    k_reset <<<32, 256>>>();                        // launch 1
    k_S     <<<N_TOK / 256, 256>>>(x);              // launch 2
    k_E2    <<<64, 128>>>(emb);                     // launch 3 (E2 + cvt fused)
    k_mma   <<<N_TOK / 128, 384, SMEM_DYN>>>(x);    // launch 4 -> ncu capture
    k_refine<<<N_TOK / 8, 256>>>(x, emb);
    k_quant <<<QPARTS, 256>>>(x, emb, out + 1);
    if (has_full)
        k_enc<<<N_TOK / 8, 256>>>(out);
    else if (enc_elems > 0)
        cudaMemsetAsync(out + ENC_OFF, 0, (size_t)enc_elems * sizeof(float), 0);
    k_final <<<1, 256>>>(out, has_full);
}